// round 2
// baseline (speedup 1.0000x reference)
#include <cuda_runtime.h>
#include <cstdint>

#define D_MODEL 1024
#define NHEAD 16
#define HEAD_DIM 64
#define BATCH 4
#define SEQ 2048
#define MTOK (BATCH*SEQ)   // 8192

// ---------------- scratch (static device globals: allocation-free) ----------
__device__ float g_q[(size_t)BATCH*NHEAD*SEQ*HEAD_DIM];   // [B,H,S,Dh]
__device__ float g_k[(size_t)BATCH*NHEAD*SEQ*HEAD_DIM];
__device__ float g_v[(size_t)BATCH*NHEAD*SEQ*HEAD_DIM];
__device__ float g_ctx[(size_t)MTOK*D_MODEL];             // [B,S,D]

// ---------------- helpers ---------------------------------------------------
__device__ __forceinline__ uint32_t f2t(float x) {
    uint32_t u;
    asm("cvt.rna.tf32.f32 %0, %1;" : "=r"(u) : "f"(x));
    return u;
}

// D = A(16x8,row) * B(8x8,col) + D, tf32 in, f32 accum
__device__ __forceinline__ void mma8(float* c, const uint32_t* a, const uint32_t* b) {
    asm volatile(
        "mma.sync.aligned.m16n8k8.row.col.f32.tf32.tf32.f32 "
        "{%0,%1,%2,%3}, {%4,%5,%6,%7}, {%8,%9}, {%0,%1,%2,%3};\n"
        : "+f"(c[0]), "+f"(c[1]), "+f"(c[2]), "+f"(c[3])
        : "r"(a[0]), "r"(a[1]), "r"(a[2]), "r"(a[3]), "r"(b[0]), "r"(b[1]));
}

// ---------------- GEMM: C[M,N] = A[M,K] @ W[K,N] + bias ---------------------
// MODE 0: A = x, scatter outputs into g_q/g_k/g_v ([B,H,S,Dh] layout)
// MODE 1: A = g_ctx, plain row-major store into C
template<int MODE>
__global__ void __launch_bounds__(256)
gemm_tf32(const float* __restrict__ A, const float* __restrict__ W,
          const float* __restrict__ bias, float* __restrict__ C,
          int N, int K)
{
    __shared__ uint32_t As[128][36];    // pad +4: a-frag loads conflict-free
    __shared__ uint32_t Ws[32][136];    // pad +8: b-frag loads conflict-free

    const int m0 = blockIdx.y * 128, n0 = blockIdx.x * 128;
    const int tid  = threadIdx.x;
    const int warp = tid >> 5, lane = tid & 31;
    const int mw = warp >> 1, nw = warp & 1;      // 4 x 2 warp grid
    const int g  = lane >> 2, qq = lane & 3;

    const float* Ag = (MODE == 1) ? g_ctx : A;

    float acc[2][8][4];
#pragma unroll
    for (int i = 0; i < 2; i++)
#pragma unroll
        for (int j = 0; j < 8; j++)
#pragma unroll
            for (int r = 0; r < 4; r++) acc[i][j][r] = 0.f;

    for (int kt = 0; kt < K; kt += 32) {
        __syncthreads();
        // A tile: 128 x 32 (1024 float4, 4 per thread)
#pragma unroll
        for (int i = 0; i < 4; i++) {
            int f = tid + i * 256;
            int row = f >> 3, c4 = (f & 7) << 2;
            float4 v = *reinterpret_cast<const float4*>(Ag + (size_t)(m0 + row) * K + kt + c4);
            uint4 u = make_uint4(f2t(v.x), f2t(v.y), f2t(v.z), f2t(v.w));
            *reinterpret_cast<uint4*>(&As[row][c4]) = u;
        }
        // W tile: 32 x 128
#pragma unroll
        for (int i = 0; i < 4; i++) {
            int f = tid + i * 256;
            int row = f >> 5, c4 = (f & 31) << 2;
            float4 v = *reinterpret_cast<const float4*>(W + (size_t)(kt + row) * N + n0 + c4);
            uint4 u = make_uint4(f2t(v.x), f2t(v.y), f2t(v.z), f2t(v.w));
            *reinterpret_cast<uint4*>(&Ws[row][c4]) = u;
        }
        __syncthreads();

#pragma unroll
        for (int kc = 0; kc < 4; kc++) {
            uint32_t af[2][4], bf[8][2];
#pragma unroll
            for (int mt = 0; mt < 2; mt++) {
                int r = mw * 32 + mt * 16;
                af[mt][0] = As[r + g    ][kc * 8 + qq    ];
                af[mt][1] = As[r + g + 8][kc * 8 + qq    ];
                af[mt][2] = As[r + g    ][kc * 8 + qq + 4];
                af[mt][3] = As[r + g + 8][kc * 8 + qq + 4];
            }
#pragma unroll
            for (int nt = 0; nt < 8; nt++) {
                int c = nw * 64 + nt * 8 + g;
                bf[nt][0] = Ws[kc * 8 + qq    ][c];
                bf[nt][1] = Ws[kc * 8 + qq + 4][c];
            }
#pragma unroll
            for (int mt = 0; mt < 2; mt++)
#pragma unroll
                for (int nt = 0; nt < 8; nt++)
                    mma8(acc[mt][nt], af[mt], bf[nt]);
        }
    }

    // epilogue
#pragma unroll
    for (int mt = 0; mt < 2; mt++) {
#pragma unroll
        for (int nt = 0; nt < 8; nt++) {
#pragma unroll
            for (int r = 0; r < 4; r++) {
                int row = m0 + mw * 32 + mt * 16 + g + ((r >= 2) ? 8 : 0);
                int col = n0 + nw * 64 + nt * 8 + 2 * qq + (r & 1);
                float val = acc[mt][nt][r] + __ldg(bias + col);
                if (MODE == 0) {
                    int c = col >> 10;            // 0:q 1:k 2:v
                    int h = (col >> 6) & 15;
                    int d = col & 63;
                    int b = row >> 11;
                    int s = row & 2047;
                    size_t idx = ((size_t)((b * NHEAD + h) * SEQ + s)) * HEAD_DIM + d;
                    float* dst = (c == 0) ? g_q : (c == 1) ? g_k : g_v;
                    dst[idx] = val;
                } else {
                    C[(size_t)row * N + col] = val;
                }
            }
        }
    }
}

// ---------------- flash attention -------------------------------------------
// grid: (S/64, H, B); block 128 (4 warps, 16 query rows each)
__global__ void __launch_bounds__(128)
attn_tf32()
{
    extern __shared__ __align__(16) uint32_t sm[];
    uint32_t (*Qs)[68] = reinterpret_cast<uint32_t(*)[68]>(sm);
    uint32_t (*Ks)[68] = reinterpret_cast<uint32_t(*)[68]>(sm + 64 * 68);
    uint32_t (*Vs)[72] = reinterpret_cast<uint32_t(*)[72]>(sm + 2 * 64 * 68);

    const int tid = threadIdx.x, warp = tid >> 5, lane = tid & 31;
    const int g = lane >> 2, qq = lane & 3;
    uint32_t (*Ps)[68] =
        reinterpret_cast<uint32_t(*)[68]>(sm + 2 * 64 * 68 + 64 * 72 + warp * 16 * 68);

    const int qt = blockIdx.x, h = blockIdx.y, b = blockIdx.z;
    const size_t head_off = ((size_t)(b * NHEAD + h)) * SEQ * HEAD_DIM;
    const float* Qg = g_q + head_off;
    const float* Kg = g_k + head_off;
    const float* Vg = g_v + head_off;

    // load Q tile (scaled by 1/sqrt(Dh))
    const float scale = 0.125f;
#pragma unroll
    for (int i = 0; i < 8; i++) {
        int f = tid + i * 128;
        int row = f >> 4, c4 = (f & 15) << 2;
        float4 v = *reinterpret_cast<const float4*>(Qg + (size_t)(qt * 64 + row) * HEAD_DIM + c4);
        uint4 u = make_uint4(f2t(v.x * scale), f2t(v.y * scale),
                             f2t(v.z * scale), f2t(v.w * scale));
        *reinterpret_cast<uint4*>(&Qs[row][c4]) = u;
    }

    float oacc[8][4];
#pragma unroll
    for (int i = 0; i < 8; i++)
#pragma unroll
        for (int r = 0; r < 4; r++) oacc[i][r] = 0.f;
    float mrow[2] = {-1e30f, -1e30f};
    float lrow[2] = {0.f, 0.f};

    for (int kt = 0; kt < SEQ / 64; kt++) {
        __syncthreads();
        // load K,V tiles (64 x 64 each)
#pragma unroll
        for (int i = 0; i < 8; i++) {
            int f = tid + i * 128;
            int row = f >> 4, c4 = (f & 15) << 2;
            float4 v = *reinterpret_cast<const float4*>(Kg + (size_t)(kt * 64 + row) * HEAD_DIM + c4);
            *reinterpret_cast<uint4*>(&Ks[row][c4]) =
                make_uint4(f2t(v.x), f2t(v.y), f2t(v.z), f2t(v.w));
            float4 w = *reinterpret_cast<const float4*>(Vg + (size_t)(kt * 64 + row) * HEAD_DIM + c4);
            *reinterpret_cast<uint4*>(&Vs[row][c4]) =
                make_uint4(f2t(w.x), f2t(w.y), f2t(w.z), f2t(w.w));
        }
        __syncthreads();

        // S = Q K^T  (16 x 64 per warp)
        float sacc[8][4];
#pragma unroll
        for (int i = 0; i < 8; i++)
#pragma unroll
            for (int r = 0; r < 4; r++) sacc[i][r] = 0.f;

#pragma unroll
        for (int kc = 0; kc < 8; kc++) {
            uint32_t af[4];
            int r = warp * 16;
            af[0] = Qs[r + g    ][kc * 8 + qq    ];
            af[1] = Qs[r + g + 8][kc * 8 + qq    ];
            af[2] = Qs[r + g    ][kc * 8 + qq + 4];
            af[3] = Qs[r + g + 8][kc * 8 + qq + 4];
#pragma unroll
            for (int nt = 0; nt < 8; nt++) {
                uint32_t bf[2] = { Ks[nt * 8 + g][kc * 8 + qq],
                                   Ks[nt * 8 + g][kc * 8 + qq + 4] };
                mma8(sacc[nt], af, bf);
            }
        }

        // online softmax (two rows per thread: g and g+8)
#pragma unroll
        for (int rr = 0; rr < 2; rr++) {
            float mloc = -1e30f;
#pragma unroll
            for (int nt = 0; nt < 8; nt++)
                mloc = fmaxf(mloc, fmaxf(sacc[nt][rr * 2], sacc[nt][rr * 2 + 1]));
            mloc = fmaxf(mloc, __shfl_xor_sync(0xffffffffu, mloc, 1));
            mloc = fmaxf(mloc, __shfl_xor_sync(0xffffffffu, mloc, 2));
            float mnew  = fmaxf(mrow[rr], mloc);
            float alpha = __expf(mrow[rr] - mnew);
            mrow[rr] = mnew;
            float lsum = 0.f;
#pragma unroll
            for (int nt = 0; nt < 8; nt++) {
                float p0 = __expf(sacc[nt][rr * 2]     - mnew);
                float p1 = __expf(sacc[nt][rr * 2 + 1] - mnew);
                sacc[nt][rr * 2] = p0; sacc[nt][rr * 2 + 1] = p1;
                lsum += p0 + p1;
            }
            lsum += __shfl_xor_sync(0xffffffffu, lsum, 1);
            lsum += __shfl_xor_sync(0xffffffffu, lsum, 2);
            lrow[rr] = lrow[rr] * alpha + lsum;
#pragma unroll
            for (int dt = 0; dt < 8; dt++) {
                oacc[dt][rr * 2]     *= alpha;
                oacc[dt][rr * 2 + 1] *= alpha;
            }
        }

        // C-fragment -> A-fragment relayout of P via per-warp smem
#pragma unroll
        for (int nt = 0; nt < 8; nt++) {
            Ps[g    ][nt * 8 + 2 * qq    ] = f2t(sacc[nt][0]);
            Ps[g    ][nt * 8 + 2 * qq + 1] = f2t(sacc[nt][1]);
            Ps[g + 8][nt * 8 + 2 * qq    ] = f2t(sacc[nt][2]);
            Ps[g + 8][nt * 8 + 2 * qq + 1] = f2t(sacc[nt][3]);
        }
        __syncwarp();

        // O += P @ V
#pragma unroll
        for (int jc = 0; jc < 8; jc++) {
            uint32_t af[4];
            af[0] = Ps[g    ][jc * 8 + qq    ];
            af[1] = Ps[g + 8][jc * 8 + qq    ];
            af[2] = Ps[g    ][jc * 8 + qq + 4];
            af[3] = Ps[g + 8][jc * 8 + qq + 4];
#pragma unroll
            for (int dt = 0; dt < 8; dt++) {
                uint32_t bf[2] = { Vs[jc * 8 + qq    ][dt * 8 + g],
                                   Vs[jc * 8 + qq + 4][dt * 8 + g] };
                mma8(oacc[dt], af, bf);
            }
        }
    }

    // normalize and write ctx in [B,S,D] layout
#pragma unroll
    for (int rr = 0; rr < 2; rr++) {
        float inv = 1.f / lrow[rr];
        int s = qt * 64 + warp * 16 + g + rr * 8;
        size_t base = ((size_t)(b * SEQ + s)) * D_MODEL;
#pragma unroll
        for (int dt = 0; dt < 8; dt++) {
            int d0 = h * HEAD_DIM + dt * 8 + 2 * qq;
            g_ctx[base + d0]     = oacc[dt][rr * 2]     * inv;
            g_ctx[base + d0 + 1] = oacc[dt][rr * 2 + 1] * inv;
        }
    }
}

// ---------------- launch -----------------------------------------------------
static const int ATTN_SMEM = (2 * 64 * 68 + 64 * 72 + 4 * 16 * 68) * 4;  // 70656 B

extern "C" void kernel_launch(void* const* d_in, const int* in_sizes, int n_in,
                              void* d_out, int out_size)
{
    const float* x     = (const float*)d_in[0];
    const float* W_qkv = (const float*)d_in[1];
    const float* b_qkv = (const float*)d_in[2];
    const float* W_out = (const float*)d_in[3];
    const float* b_out = (const float*)d_in[4];
    float* out = (float*)d_out;

    cudaFuncSetAttribute(attn_tf32, cudaFuncAttributeMaxDynamicSharedMemorySize, ATTN_SMEM);

    // 1) QKV projection, scattered into [B,H,S,Dh]
    gemm_tf32<0><<<dim3(3 * D_MODEL / 128, MTOK / 128), 256>>>(
        x, W_qkv, b_qkv, nullptr, 3 * D_MODEL, D_MODEL);

    // 2) flash attention -> ctx [B,S,D]
    attn_tf32<<<dim3(SEQ / 64, NHEAD, BATCH), 128, ATTN_SMEM>>>();

    // 3) output projection
    gemm_tf32<1><<<dim3(D_MODEL / 128, MTOK / 128), 256>>>(
        nullptr, W_out, b_out, out, D_MODEL, D_MODEL);
}

// round 4
// speedup vs baseline: 1.1361x; 1.1361x over previous
#include <cuda_runtime.h>
#include <cstdint>

#define D_MODEL 1024
#define NHEAD 16
#define HEAD_DIM 64
#define BATCH 4
#define SEQ 2048
#define MTOK (BATCH*SEQ)   // 8192

// ---------------- scratch (static device globals: allocation-free) ----------
__device__ __align__(256) float g_q[(size_t)BATCH*NHEAD*SEQ*HEAD_DIM];   // [B,H,S,Dh]
__device__ __align__(256) float g_k[(size_t)BATCH*NHEAD*SEQ*HEAD_DIM];
__device__ __align__(256) float g_v[(size_t)BATCH*NHEAD*SEQ*HEAD_DIM];
__device__ __align__(256) float g_ctx[(size_t)MTOK*D_MODEL];             // [B,S,D]

// ---------------- helpers ---------------------------------------------------
__device__ __forceinline__ uint32_t f2t(float x) {
    uint32_t u;
    asm("cvt.rna.tf32.f32 %0, %1;" : "=r"(u) : "f"(x));
    return u;
}
__device__ __forceinline__ uint32_t sa(const void* p) {
    return (uint32_t)__cvta_generic_to_shared(p);
}
__device__ __forceinline__ void cpa16(uint32_t dst, const void* src) {
    asm volatile("cp.async.cg.shared.global [%0], [%1], 16;\n" :: "r"(dst), "l"(src));
}
#define CP_COMMIT asm volatile("cp.async.commit_group;\n" ::: "memory")
#define CP_WAIT0  asm volatile("cp.async.wait_group 0;\n" ::: "memory")

// D = A(16x8,row) * B(8x8,col) + D, tf32 in, f32 accum
__device__ __forceinline__ void mma8(float* c, const uint32_t* a, const uint32_t* b) {
    asm volatile(
        "mma.sync.aligned.m16n8k8.row.col.f32.tf32.tf32.f32 "
        "{%0,%1,%2,%3}, {%4,%5,%6,%7}, {%8,%9}, {%0,%1,%2,%3};\n"
        : "+f"(c[0]), "+f"(c[1]), "+f"(c[2]), "+f"(c[3])
        : "r"(a[0]), "r"(a[1]), "r"(a[2]), "r"(a[3]), "r"(b[0]), "r"(b[1]));
}

// ---------------- GEMM: C[M,N] = A[M,K] @ W[K,N] + bias ---------------------
// Double-buffered cp.async pipeline. MODE 0: scatter into g_q/g_k/g_v.
// MODE 1: A = g_ctx, row-major store.
#define GA_SZ (128*36)
#define GW_SZ (32*136)
static const int GEMM_SMEM = (2*GA_SZ + 2*GW_SZ) * 4;   // 71680 B

template<int MODE>
__global__ void __launch_bounds__(256, 2)
gemm_tf32(const float* __restrict__ A, const float* __restrict__ W,
          const float* __restrict__ bias, float* __restrict__ C,
          int N, int K)
{
    extern __shared__ float smg[];
    const int m0 = blockIdx.y * 128, n0 = blockIdx.x * 128;
    const int tid  = threadIdx.x;
    const int warp = tid >> 5, lane = tid & 31;
    const int mw = warp >> 1, nw = warp & 1;      // 4 x 2 warp grid
    const int g  = lane >> 2, qq = lane & 3;

    const float* Ag = (MODE == 1) ? g_ctx : A;

    float acc[2][8][4];
#pragma unroll
    for (int i = 0; i < 2; i++)
#pragma unroll
        for (int j = 0; j < 8; j++)
#pragma unroll
            for (int r = 0; r < 4; r++) acc[i][j][r] = 0.f;

    auto load_tiles = [&](int kel, int buf) {
        float* Ab = smg + buf * GA_SZ;
        float* Wb = smg + 2 * GA_SZ + buf * GW_SZ;
#pragma unroll
        for (int i = 0; i < 4; i++) {
            int f = tid + i * 256;
            int row = f >> 3, c4 = (f & 7) << 2;
            cpa16(sa(Ab + row * 36 + c4), Ag + (size_t)(m0 + row) * K + kel + c4);
        }
#pragma unroll
        for (int i = 0; i < 4; i++) {
            int f = tid + i * 256;
            int row = f >> 5, c4 = (f & 31) << 2;
            cpa16(sa(Wb + row * 136 + c4), W + (size_t)(kel + row) * N + n0 + c4);
        }
        CP_COMMIT;
    };

    const int NT = K >> 5;
    load_tiles(0, 0);

    for (int kt = 0; kt < NT; kt++) {
        CP_WAIT0;
        __syncthreads();
        if (kt + 1 < NT) load_tiles((kt + 1) << 5, (kt + 1) & 1);

        const float* Ab = smg + (kt & 1) * GA_SZ;
        const float* Wb = smg + 2 * GA_SZ + (kt & 1) * GW_SZ;

#pragma unroll
        for (int kc = 0; kc < 4; kc++) {
            uint32_t af[2][4], bf[8][2];
#pragma unroll
            for (int mt = 0; mt < 2; mt++) {
                int r = mw * 32 + mt * 16;
                af[mt][0] = f2t(Ab[(r + g    ) * 36 + kc * 8 + qq    ]);
                af[mt][1] = f2t(Ab[(r + g + 8) * 36 + kc * 8 + qq    ]);
                af[mt][2] = f2t(Ab[(r + g    ) * 36 + kc * 8 + qq + 4]);
                af[mt][3] = f2t(Ab[(r + g + 8) * 36 + kc * 8 + qq + 4]);
            }
#pragma unroll
            for (int nt = 0; nt < 8; nt++) {
                int c = nw * 64 + nt * 8 + g;
                bf[nt][0] = f2t(Wb[(kc * 8 + qq    ) * 136 + c]);
                bf[nt][1] = f2t(Wb[(kc * 8 + qq + 4) * 136 + c]);
            }
#pragma unroll
            for (int mt = 0; mt < 2; mt++)
#pragma unroll
                for (int nt = 0; nt < 8; nt++)
                    mma8(acc[mt][nt], af[mt], bf[nt]);
        }
    }

    // epilogue (paired stores: c-frag regs {0,1} and {2,3} are col-adjacent)
#pragma unroll
    for (int mt = 0; mt < 2; mt++) {
#pragma unroll
        for (int nt = 0; nt < 8; nt++) {
            int col = n0 + nw * 64 + nt * 8 + 2 * qq;
            float b0 = __ldg(bias + col), b1 = __ldg(bias + col + 1);
#pragma unroll
            for (int half = 0; half < 2; half++) {
                int row = m0 + mw * 32 + mt * 16 + g + half * 8;
                float2 val = make_float2(acc[mt][nt][half * 2    ] + b0,
                                         acc[mt][nt][half * 2 + 1] + b1);
                if (MODE == 0) {
                    int c = col >> 10;            // 0:q 1:k 2:v
                    int h = (col >> 6) & 15;
                    int d = col & 63;
                    int b = row >> 11;
                    int s = row & 2047;
                    size_t idx = ((size_t)((b * NHEAD + h) * SEQ + s)) * HEAD_DIM + d;
                    float* dst = (c == 0) ? g_q : (c == 1) ? g_k : g_v;
                    *reinterpret_cast<float2*>(dst + idx) = val;
                } else {
                    *reinterpret_cast<float2*>(C + (size_t)row * N + col) = val;
                }
            }
        }
    }
}

// ---------------- flash attention -------------------------------------------
// grid: (S/128, H, B); block 256 (8 warps, 16 query rows each).
// Q tile 128, K/V tiles 64, double-buffered cp.async.
#define AQ_SZ (128*68)
#define AK_SZ (64*68)
#define AV_SZ (64*72)
#define AP_SZ (16*68)
static const int ATTN_SMEM = (AQ_SZ + 2*AK_SZ + 2*AV_SZ + 8*AP_SZ) * 4;  // 141312 B

__global__ void __launch_bounds__(256)
attn_tf32()
{
    extern __shared__ float sma[];
    float* Qs = sma;
    float* Kbase = sma + AQ_SZ;
    float* Vbase = sma + AQ_SZ + 2 * AK_SZ;

    const int tid = threadIdx.x, warp = tid >> 5, lane = tid & 31;
    const int g = lane >> 2, qq = lane & 3;
    float* Ps = sma + AQ_SZ + 2 * AK_SZ + 2 * AV_SZ + warp * AP_SZ;

    const int qt = blockIdx.x, h = blockIdx.y, b = blockIdx.z;
    const size_t head_off = ((size_t)(b * NHEAD + h)) * SEQ * HEAD_DIM;
    const float* Qg = g_q + head_off;
    const float* Kg = g_k + head_off;
    const float* Vg = g_v + head_off;

    auto load_kv = [&](int kt, int buf) {
        float* Kb = Kbase + buf * AK_SZ;
        float* Vb = Vbase + buf * AV_SZ;
#pragma unroll
        for (int i = 0; i < 4; i++) {
            int f = tid + i * 256;
            int row = f >> 4, c4 = (f & 15) << 2;
            const size_t go = (size_t)(kt * 64 + row) * HEAD_DIM + c4;
            cpa16(sa(Kb + row * 68 + c4), Kg + go);
            cpa16(sa(Vb + row * 72 + c4), Vg + go);
        }
        CP_COMMIT;
    };

    // Q tile (raw fp32; converted at fragment load)
#pragma unroll
    for (int i = 0; i < 8; i++) {
        int f = tid + i * 256;
        int row = f >> 4, c4 = (f & 15) << 2;
        cpa16(sa(Qs + row * 68 + c4), Qg + (size_t)(qt * 128 + row) * HEAD_DIM + c4);
    }
    load_kv(0, 0);

    float oacc[8][4];
#pragma unroll
    for (int i = 0; i < 8; i++)
#pragma unroll
        for (int r = 0; r < 4; r++) oacc[i][r] = 0.f;
    float mrow[2] = {-1e30f, -1e30f};
    float lrow[2] = {0.f, 0.f};

    const int NT = SEQ / 64;
    for (int kt = 0; kt < NT; kt++) {
        CP_WAIT0;
        __syncthreads();
        if (kt + 1 < NT) load_kv(kt + 1, (kt + 1) & 1);

        const float* Kb = Kbase + (kt & 1) * AK_SZ;
        const float* Vb = Vbase + (kt & 1) * AV_SZ;

        // S = Q K^T  (16 x 64 per warp)
        float sacc[8][4];
#pragma unroll
        for (int i = 0; i < 8; i++)
#pragma unroll
            for (int r = 0; r < 4; r++) sacc[i][r] = 0.f;

#pragma unroll
        for (int kc = 0; kc < 8; kc++) {
            uint32_t af[4];
            int r = warp * 16;
            af[0] = f2t(Qs[(r + g    ) * 68 + kc * 8 + qq    ]);
            af[1] = f2t(Qs[(r + g + 8) * 68 + kc * 8 + qq    ]);
            af[2] = f2t(Qs[(r + g    ) * 68 + kc * 8 + qq + 4]);
            af[3] = f2t(Qs[(r + g + 8) * 68 + kc * 8 + qq + 4]);
#pragma unroll
            for (int nt = 0; nt < 8; nt++) {
                uint32_t bf[2] = { f2t(Kb[(nt * 8 + g) * 68 + kc * 8 + qq    ]),
                                   f2t(Kb[(nt * 8 + g) * 68 + kc * 8 + qq + 4]) };
                mma8(sacc[nt], af, bf);
            }
        }

        // apply 1/sqrt(Dh) scale (exact power of two)
#pragma unroll
        for (int nt = 0; nt < 8; nt++)
#pragma unroll
            for (int r = 0; r < 4; r++) sacc[nt][r] *= 0.125f;

        // online softmax (two rows per thread: g and g+8)
#pragma unroll
        for (int rr = 0; rr < 2; rr++) {
            float mloc = -1e30f;
#pragma unroll
            for (int nt = 0; nt < 8; nt++)
                mloc = fmaxf(mloc, fmaxf(sacc[nt][rr * 2], sacc[nt][rr * 2 + 1]));
            mloc = fmaxf(mloc, __shfl_xor_sync(0xffffffffu, mloc, 1));
            mloc = fmaxf(mloc, __shfl_xor_sync(0xffffffffu, mloc, 2));
            float mnew  = fmaxf(mrow[rr], mloc);
            float alpha = __expf(mrow[rr] - mnew);
            mrow[rr] = mnew;
            float lsum = 0.f;
#pragma unroll
            for (int nt = 0; nt < 8; nt++) {
                float p0 = __expf(sacc[nt][rr * 2]     - mnew);
                float p1 = __expf(sacc[nt][rr * 2 + 1] - mnew);
                sacc[nt][rr * 2] = p0; sacc[nt][rr * 2 + 1] = p1;
                lsum += p0 + p1;
            }
            lsum += __shfl_xor_sync(0xffffffffu, lsum, 1);
            lsum += __shfl_xor_sync(0xffffffffu, lsum, 2);
            lrow[rr] = lrow[rr] * alpha + lsum;
#pragma unroll
            for (int dt = 0; dt < 8; dt++) {
                oacc[dt][rr * 2]     *= alpha;
                oacc[dt][rr * 2 + 1] *= alpha;
            }
        }

        // C-fragment -> A-fragment relayout of P via per-warp smem
#pragma unroll
        for (int nt = 0; nt < 8; nt++) {
            Ps[(g    ) * 68 + nt * 8 + 2 * qq    ] = __uint_as_float(f2t(sacc[nt][0]));
            Ps[(g    ) * 68 + nt * 8 + 2 * qq + 1] = __uint_as_float(f2t(sacc[nt][1]));
            Ps[(g + 8) * 68 + nt * 8 + 2 * qq    ] = __uint_as_float(f2t(sacc[nt][2]));
            Ps[(g + 8) * 68 + nt * 8 + 2 * qq + 1] = __uint_as_float(f2t(sacc[nt][3]));
        }
        __syncwarp();

        // O += P @ V
#pragma unroll
        for (int jc = 0; jc < 8; jc++) {
            uint32_t af[4];
            af[0] = __float_as_uint(Ps[(g    ) * 68 + jc * 8 + qq    ]);
            af[1] = __float_as_uint(Ps[(g + 8) * 68 + jc * 8 + qq    ]);
            af[2] = __float_as_uint(Ps[(g    ) * 68 + jc * 8 + qq + 4]);
            af[3] = __float_as_uint(Ps[(g + 8) * 68 + jc * 8 + qq + 4]);
#pragma unroll
            for (int dt = 0; dt < 8; dt++) {
                uint32_t bf[2] = { f2t(Vb[(jc * 8 + qq    ) * 72 + dt * 8 + g]),
                                   f2t(Vb[(jc * 8 + qq + 4) * 72 + dt * 8 + g]) };
                mma8(oacc[dt], af, bf);
            }
        }
    }

    // normalize and write ctx in [B,S,D] layout
#pragma unroll
    for (int rr = 0; rr < 2; rr++) {
        float inv = 1.f / lrow[rr];
        int s = qt * 128 + warp * 16 + g + rr * 8;
        size_t base = ((size_t)(b * SEQ + s)) * D_MODEL;
#pragma unroll
        for (int dt = 0; dt < 8; dt++) {
            int d0 = h * HEAD_DIM + dt * 8 + 2 * qq;
            float2 val = make_float2(oacc[dt][rr * 2] * inv, oacc[dt][rr * 2 + 1] * inv);
            *reinterpret_cast<float2*>(g_ctx + base + d0) = val;
        }
    }
}

// ---------------- launch -----------------------------------------------------
extern "C" void kernel_launch(void* const* d_in, const int* in_sizes, int n_in,
                              void* d_out, int out_size)
{
    const float* x     = (const float*)d_in[0];
    const float* W_qkv = (const float*)d_in[1];
    const float* b_qkv = (const float*)d_in[2];
    const float* W_out = (const float*)d_in[3];
    const float* b_out = (const float*)d_in[4];
    float* out = (float*)d_out;

    cudaFuncSetAttribute(gemm_tf32<0>, cudaFuncAttributeMaxDynamicSharedMemorySize, GEMM_SMEM);
    cudaFuncSetAttribute(gemm_tf32<1>, cudaFuncAttributeMaxDynamicSharedMemorySize, GEMM_SMEM);
    cudaFuncSetAttribute(attn_tf32,    cudaFuncAttributeMaxDynamicSharedMemorySize, ATTN_SMEM);

    // 1) QKV projection, scattered into [B,H,S,Dh]
    gemm_tf32<0><<<dim3(3 * D_MODEL / 128, MTOK / 128), 256, GEMM_SMEM>>>(
        x, W_qkv, b_qkv, nullptr, 3 * D_MODEL, D_MODEL);

    // 2) flash attention -> ctx [B,S,D]
    attn_tf32<<<dim3(SEQ / 128, NHEAD, BATCH), 256, ATTN_SMEM>>>();

    // 3) output projection
    gemm_tf32<1><<<dim3(D_MODEL / 128, MTOK / 128), 256, GEMM_SMEM>>>(
        nullptr, W_out, b_out, out, D_MODEL, D_MODEL);
}

// round 6
// speedup vs baseline: 1.2478x; 1.0984x over previous
#include <cuda_runtime.h>
#include <cstdint>

#define D_MODEL 1024
#define NHEAD 16
#define HEAD_DIM 64
#define BATCH 4
#define SEQ 2048
#define MTOK (BATCH*SEQ)   // 8192

// ---------------- scratch (static device globals: allocation-free) ----------
__device__ __align__(256) float g_q[(size_t)BATCH*NHEAD*SEQ*HEAD_DIM];   // [B,H,S,Dh] tf32-rounded
__device__ __align__(256) float g_k[(size_t)BATCH*NHEAD*SEQ*HEAD_DIM];
__device__ __align__(256) float g_v[(size_t)BATCH*NHEAD*SEQ*HEAD_DIM];
__device__ __align__(256) float g_ctx[(size_t)MTOK*D_MODEL];             // [B,S,D] tf32-rounded
__device__ __align__(256) float g_x[(size_t)MTOK*D_MODEL];               // tf32-rounded inputs
__device__ __align__(256) float g_wqkv[(size_t)D_MODEL*3*D_MODEL];
__device__ __align__(256) float g_wout[(size_t)D_MODEL*D_MODEL];

// ---------------- helpers ---------------------------------------------------
__device__ __forceinline__ uint32_t f2t(float x) {
    uint32_t u;
    asm("cvt.rna.tf32.f32 %0, %1;" : "=r"(u) : "f"(x));
    return u;
}
__device__ __forceinline__ float ex2(float x) {
    float y;
    asm("ex2.approx.f32 %0, %1;" : "=f"(y) : "f"(x));
    return y;
}
__device__ __forceinline__ uint32_t sa(const void* p) {
    return (uint32_t)__cvta_generic_to_shared(p);
}
__device__ __forceinline__ void cpa16(uint32_t dst, const void* src) {
    asm volatile("cp.async.cg.shared.global [%0], [%1], 16;\n" :: "r"(dst), "l"(src));
}
#define CP_COMMIT asm volatile("cp.async.commit_group;\n" ::: "memory")
#define CP_WAIT0  asm volatile("cp.async.wait_group 0;\n" ::: "memory")

// D = A(16x8,row) * B(8x8,col) + D, tf32 in, f32 accum
__device__ __forceinline__ void mma8(float* c, const uint32_t* a, const uint32_t* b) {
    asm volatile(
        "mma.sync.aligned.m16n8k8.row.col.f32.tf32.tf32.f32 "
        "{%0,%1,%2,%3}, {%4,%5,%6,%7}, {%8,%9}, {%0,%1,%2,%3};\n"
        : "+f"(c[0]), "+f"(c[1]), "+f"(c[2]), "+f"(c[3])
        : "r"(a[0]), "r"(a[1]), "r"(a[2]), "r"(a[3]), "r"(b[0]), "r"(b[1]));
}

// ---------------- prep: round fp32 -> tf32 (rna), stored as fp32 bits -------
__global__ void round_tf32_k(const float* __restrict__ src, float* __restrict__ dst, int n4)
{
    int stride = gridDim.x * blockDim.x;
    for (int i = blockIdx.x * blockDim.x + threadIdx.x; i < n4; i += stride) {
        float4 v = reinterpret_cast<const float4*>(src)[i];
        float4 o;
        o.x = __uint_as_float(f2t(v.x));
        o.y = __uint_as_float(f2t(v.y));
        o.z = __uint_as_float(f2t(v.z));
        o.w = __uint_as_float(f2t(v.w));
        reinterpret_cast<float4*>(dst)[i] = o;
    }
}

// ---------------- GEMM: C[M,N] = A[M,K] @ W[K,N] + bias ---------------------
// Operands are pre-rounded to tf32; mainloop has NO cvt.
// MODE 0: A=g_x, W=g_wqkv, scatter tf32-rounded into g_q/g_k/g_v.
// MODE 1: A=g_ctx, W=g_wout, plain fp32 store into C.
#define GA_SZ (128*36)
#define GW_SZ (32*136)
static const int GEMM_SMEM = (2*GA_SZ + 2*GW_SZ) * 4;   // 71680 B

template<int MODE>
__global__ void __launch_bounds__(256, 2)
gemm_tf32(const float* __restrict__ bias, float* __restrict__ C, int N, int K)
{
    extern __shared__ float smg[];
    const int m0 = blockIdx.y * 128, n0 = blockIdx.x * 128;
    const int tid  = threadIdx.x;
    const int warp = tid >> 5, lane = tid & 31;
    const int mw = warp >> 1, nw = warp & 1;      // 4 x 2 warp grid
    const int g  = lane >> 2, qq = lane & 3;

    const float* Ag = (MODE == 1) ? g_ctx : g_x;
    const float* W  = (MODE == 1) ? g_wout : g_wqkv;

    float acc[2][8][4];
#pragma unroll
    for (int i = 0; i < 2; i++)
#pragma unroll
        for (int j = 0; j < 8; j++)
#pragma unroll
            for (int r = 0; r < 4; r++) acc[i][j][r] = 0.f;

    auto load_tiles = [&](int kel, int buf) {
        float* Ab = smg + buf * GA_SZ;
        float* Wb = smg + 2 * GA_SZ + buf * GW_SZ;
#pragma unroll
        for (int i = 0; i < 4; i++) {
            int f = tid + i * 256;
            int row = f >> 3, c4 = (f & 7) << 2;
            cpa16(sa(Ab + row * 36 + c4), Ag + (size_t)(m0 + row) * K + kel + c4);
        }
#pragma unroll
        for (int i = 0; i < 4; i++) {
            int f = tid + i * 256;
            int row = f >> 5, c4 = (f & 31) << 2;
            cpa16(sa(Wb + row * 136 + c4), W + (size_t)(kel + row) * N + n0 + c4);
        }
        CP_COMMIT;
    };

    const int NT = K >> 5;
    load_tiles(0, 0);

    for (int kt = 0; kt < NT; kt++) {
        CP_WAIT0;
        __syncthreads();
        if (kt + 1 < NT) load_tiles((kt + 1) << 5, (kt + 1) & 1);

        const uint32_t* Ab = reinterpret_cast<const uint32_t*>(smg + (kt & 1) * GA_SZ);
        const uint32_t* Wb = reinterpret_cast<const uint32_t*>(smg + 2 * GA_SZ + (kt & 1) * GW_SZ);

#pragma unroll
        for (int kc = 0; kc < 4; kc++) {
            uint32_t af[2][4], bf[8][2];
#pragma unroll
            for (int mt = 0; mt < 2; mt++) {
                int r = mw * 32 + mt * 16;
                af[mt][0] = Ab[(r + g    ) * 36 + kc * 8 + qq    ];
                af[mt][1] = Ab[(r + g + 8) * 36 + kc * 8 + qq    ];
                af[mt][2] = Ab[(r + g    ) * 36 + kc * 8 + qq + 4];
                af[mt][3] = Ab[(r + g + 8) * 36 + kc * 8 + qq + 4];
            }
#pragma unroll
            for (int nt = 0; nt < 8; nt++) {
                int c = nw * 64 + nt * 8 + g;
                bf[nt][0] = Wb[(kc * 8 + qq    ) * 136 + c];
                bf[nt][1] = Wb[(kc * 8 + qq + 4) * 136 + c];
            }
#pragma unroll
            for (int mt = 0; mt < 2; mt++)
#pragma unroll
                for (int nt = 0; nt < 8; nt++)
                    mma8(acc[mt][nt], af[mt], bf[nt]);
        }
    }

    // epilogue
#pragma unroll
    for (int mt = 0; mt < 2; mt++) {
#pragma unroll
        for (int nt = 0; nt < 8; nt++) {
            int col = n0 + nw * 64 + nt * 8 + 2 * qq;
            float b0 = __ldg(bias + col), b1 = __ldg(bias + col + 1);
#pragma unroll
            for (int half = 0; half < 2; half++) {
                int row = m0 + mw * 32 + mt * 16 + g + half * 8;
                float v0 = acc[mt][nt][half * 2    ] + b0;
                float v1 = acc[mt][nt][half * 2 + 1] + b1;
                if (MODE == 0) {
                    // round to tf32 here: attention feeds these to MMA raw
                    float2 val = make_float2(__uint_as_float(f2t(v0)),
                                             __uint_as_float(f2t(v1)));
                    int c = col >> 10;            // 0:q 1:k 2:v
                    int h = (col >> 6) & 15;
                    int d = col & 63;
                    int b = row >> 11;
                    int s = row & 2047;
                    size_t idx = ((size_t)((b * NHEAD + h) * SEQ + s)) * HEAD_DIM + d;
                    float* dst = (c == 0) ? g_q : (c == 1) ? g_k : g_v;
                    *reinterpret_cast<float2*>(dst + idx) = val;
                } else {
                    *reinterpret_cast<float2*>(C + (size_t)row * N + col) =
                        make_float2(v0, v1);
                }
            }
        }
    }
}

// ---------------- flash attention -------------------------------------------
// grid: (S/128, H, B); block 256 (8 warps, 16 query rows each).
// Q tile 128, K/V tiles 64, double-buffered cp.async. Inputs pre-rounded tf32.
#define AQ_SZ (128*68)
#define AK_SZ (64*68)
#define AV_SZ (64*72)
#define AP_SZ (16*68)
static const int ATTN_SMEM = (AQ_SZ + 2*AK_SZ + 2*AV_SZ + 8*AP_SZ) * 4;  // 141312 B

__global__ void __launch_bounds__(256)
attn_tf32()
{
    extern __shared__ float sma[];
    float* Qs = sma;
    float* Kbase = sma + AQ_SZ;
    float* Vbase = sma + AQ_SZ + 2 * AK_SZ;

    const int tid = threadIdx.x, warp = tid >> 5, lane = tid & 31;
    const int g = lane >> 2, qq = lane & 3;
    float* Ps = sma + AQ_SZ + 2 * AK_SZ + 2 * AV_SZ + warp * AP_SZ;

    const int qt = blockIdx.x, h = blockIdx.y, b = blockIdx.z;
    const size_t head_off = ((size_t)(b * NHEAD + h)) * SEQ * HEAD_DIM;
    const float* Qg = g_q + head_off;
    const float* Kg = g_k + head_off;
    const float* Vg = g_v + head_off;

    auto load_kv = [&](int kt, int buf) {
        float* Kb = Kbase + buf * AK_SZ;
        float* Vb = Vbase + buf * AV_SZ;
#pragma unroll
        for (int i = 0; i < 4; i++) {
            int f = tid + i * 256;
            int row = f >> 4, c4 = (f & 15) << 2;
            const size_t go = (size_t)(kt * 64 + row) * HEAD_DIM + c4;
            cpa16(sa(Kb + row * 68 + c4), Kg + go);
            cpa16(sa(Vb + row * 72 + c4), Vg + go);
        }
        CP_COMMIT;
    };

#pragma unroll
    for (int i = 0; i < 8; i++) {
        int f = tid + i * 256;
        int row = f >> 4, c4 = (f & 15) << 2;
        cpa16(sa(Qs + row * 68 + c4), Qg + (size_t)(qt * 128 + row) * HEAD_DIM + c4);
    }
    load_kv(0, 0);

    float oacc[8][4];
#pragma unroll
    for (int i = 0; i < 8; i++)
#pragma unroll
        for (int r = 0; r < 4; r++) oacc[i][r] = 0.f;
    float mrow[2] = {-1e30f, -1e30f};
    float lrow[2] = {0.f, 0.f};

    // scores scaled by 1/sqrt(Dh) * log2(e), exp via ex2
    const float SCALE = 0.125f * 1.4426950408889634f;

    const int NT = SEQ / 64;
    for (int kt = 0; kt < NT; kt++) {
        CP_WAIT0;
        __syncthreads();
        if (kt + 1 < NT) load_kv(kt + 1, (kt + 1) & 1);

        const uint32_t* Kb = reinterpret_cast<const uint32_t*>(Kbase + (kt & 1) * AK_SZ);
        const uint32_t* Vb = reinterpret_cast<const uint32_t*>(Vbase + (kt & 1) * AV_SZ);
        const uint32_t* Qu = reinterpret_cast<const uint32_t*>(Qs);

        // S = Q K^T  (16 x 64 per warp)
        float sacc[8][4];
#pragma unroll
        for (int i = 0; i < 8; i++)
#pragma unroll
            for (int r = 0; r < 4; r++) sacc[i][r] = 0.f;

#pragma unroll
        for (int kc = 0; kc < 8; kc++) {
            uint32_t af[4];
            int r = warp * 16;
            af[0] = Qu[(r + g    ) * 68 + kc * 8 + qq    ];
            af[1] = Qu[(r + g + 8) * 68 + kc * 8 + qq    ];
            af[2] = Qu[(r + g    ) * 68 + kc * 8 + qq + 4];
            af[3] = Qu[(r + g + 8) * 68 + kc * 8 + qq + 4];
#pragma unroll
            for (int nt = 0; nt < 8; nt++) {
                uint32_t bf[2] = { Kb[(nt * 8 + g) * 68 + kc * 8 + qq    ],
                                   Kb[(nt * 8 + g) * 68 + kc * 8 + qq + 4] };
                mma8(sacc[nt], af, bf);
            }
        }

#pragma unroll
        for (int nt = 0; nt < 8; nt++)
#pragma unroll
            for (int r = 0; r < 4; r++) sacc[nt][r] *= SCALE;

        // online softmax in log2 domain (two rows per thread: g and g+8)
#pragma unroll
        for (int rr = 0; rr < 2; rr++) {
            float mloc = -1e30f;
#pragma unroll
            for (int nt = 0; nt < 8; nt++)
                mloc = fmaxf(mloc, fmaxf(sacc[nt][rr * 2], sacc[nt][rr * 2 + 1]));
            mloc = fmaxf(mloc, __shfl_xor_sync(0xffffffffu, mloc, 1));
            mloc = fmaxf(mloc, __shfl_xor_sync(0xffffffffu, mloc, 2));
            float mnew  = fmaxf(mrow[rr], mloc);
            float alpha = ex2(mrow[rr] - mnew);
            mrow[rr] = mnew;
            float lsum = 0.f;
#pragma unroll
            for (int nt = 0; nt < 8; nt++) {
                float p0 = ex2(sacc[nt][rr * 2]     - mnew);
                float p1 = ex2(sacc[nt][rr * 2 + 1] - mnew);
                sacc[nt][rr * 2] = p0; sacc[nt][rr * 2 + 1] = p1;
                lsum += p0 + p1;
            }
            lsum += __shfl_xor_sync(0xffffffffu, lsum, 1);
            lsum += __shfl_xor_sync(0xffffffffu, lsum, 2);
            lrow[rr] = lrow[rr] * alpha + lsum;
#pragma unroll
            for (int dt = 0; dt < 8; dt++) {
                oacc[dt][rr * 2]     *= alpha;
                oacc[dt][rr * 2 + 1] *= alpha;
            }
        }

        // C-fragment -> A-fragment relayout of P via per-warp smem (rounded)
#pragma unroll
        for (int nt = 0; nt < 8; nt++) {
            Ps[(g    ) * 68 + nt * 8 + 2 * qq    ] = __uint_as_float(f2t(sacc[nt][0]));
            Ps[(g    ) * 68 + nt * 8 + 2 * qq + 1] = __uint_as_float(f2t(sacc[nt][1]));
            Ps[(g + 8) * 68 + nt * 8 + 2 * qq    ] = __uint_as_float(f2t(sacc[nt][2]));
            Ps[(g + 8) * 68 + nt * 8 + 2 * qq + 1] = __uint_as_float(f2t(sacc[nt][3]));
        }
        __syncwarp();

        // O += P @ V
#pragma unroll
        for (int jc = 0; jc < 8; jc++) {
            uint32_t af[4];
            af[0] = __float_as_uint(Ps[(g    ) * 68 + jc * 8 + qq    ]);
            af[1] = __float_as_uint(Ps[(g + 8) * 68 + jc * 8 + qq    ]);
            af[2] = __float_as_uint(Ps[(g    ) * 68 + jc * 8 + qq + 4]);
            af[3] = __float_as_uint(Ps[(g + 8) * 68 + jc * 8 + qq + 4]);
#pragma unroll
            for (int dt = 0; dt < 8; dt++) {
                uint32_t bf[2] = { Vb[(jc * 8 + qq    ) * 72 + dt * 8 + g],
                                   Vb[(jc * 8 + qq + 4) * 72 + dt * 8 + g] };
                mma8(oacc[dt], af, bf);
            }
        }
    }

    // normalize; write ctx tf32-rounded in [B,S,D] layout (feeds gemm1 raw)
#pragma unroll
    for (int rr = 0; rr < 2; rr++) {
        float inv = 1.f / lrow[rr];
        int s = qt * 128 + warp * 16 + g + rr * 8;
        size_t base = ((size_t)(b * SEQ + s)) * D_MODEL;
#pragma unroll
        for (int dt = 0; dt < 8; dt++) {
            int d0 = h * HEAD_DIM + dt * 8 + 2 * qq;
            float2 val = make_float2(
                __uint_as_float(f2t(oacc[dt][rr * 2]     * inv)),
                __uint_as_float(f2t(oacc[dt][rr * 2 + 1] * inv)));
            *reinterpret_cast<float2*>(g_ctx + base + d0) = val;
        }
    }
}

// ---------------- launch -----------------------------------------------------
extern "C" void kernel_launch(void* const* d_in, const int* in_sizes, int n_in,
                              void* d_out, int out_size)
{
    const float* x     = (const float*)d_in[0];
    const float* W_qkv = (const float*)d_in[1];
    const float* b_qkv = (const float*)d_in[2];
    const float* W_out = (const float*)d_in[3];
    const float* b_out = (const float*)d_in[4];
    float* out = (float*)d_out;

    cudaFuncSetAttribute(gemm_tf32<0>, cudaFuncAttributeMaxDynamicSharedMemorySize, GEMM_SMEM);
    cudaFuncSetAttribute(gemm_tf32<1>, cudaFuncAttributeMaxDynamicSharedMemorySize, GEMM_SMEM);
    cudaFuncSetAttribute(attn_tf32,    cudaFuncAttributeMaxDynamicSharedMemorySize, ATTN_SMEM);

    float* gx; float* gwq; float* gwo;
    cudaGetSymbolAddress((void**)&gx,  g_x);
    cudaGetSymbolAddress((void**)&gwq, g_wqkv);
    cudaGetSymbolAddress((void**)&gwo, g_wout);

    // 0) one-shot rna rounding of all tf32 operands
    round_tf32_k<<<2048, 256>>>(x,     gx,  MTOK * D_MODEL / 4);
    round_tf32_k<<<2048, 256>>>(W_qkv, gwq, D_MODEL * 3 * D_MODEL / 4);
    round_tf32_k<<<1024, 256>>>(W_out, gwo, D_MODEL * D_MODEL / 4);

    // 1) QKV projection, scattered tf32-rounded into [B,H,S,Dh]
    gemm_tf32<0><<<dim3(3 * D_MODEL / 128, MTOK / 128), 256, GEMM_SMEM>>>(
        b_qkv, nullptr, 3 * D_MODEL, D_MODEL);

    // 2) flash attention -> ctx [B,S,D]
    attn_tf32<<<dim3(SEQ / 128, NHEAD, BATCH), 256, ATTN_SMEM>>>();

    // 3) output projection (final fp32, no rounding)
    gemm_tf32<1><<<dim3(D_MODEL / 128, MTOK / 128), 256, GEMM_SMEM>>>(
        b_out, out, D_MODEL, D_MODEL);
}

// round 8
// speedup vs baseline: 2.0972x; 1.6807x over previous
#include <cuda_runtime.h>
#include <cuda_fp16.h>
#include <cstdint>

#define D_MODEL 1024
#define NHEAD 16
#define HEAD_DIM 64
#define BATCH 4
#define SEQ 2048
#define MTOK (BATCH*SEQ)   // 8192

// ---------------- scratch (static device globals: allocation-free) ----------
__device__ __align__(256) __half g_q[(size_t)BATCH*NHEAD*SEQ*HEAD_DIM];   // [B,H,S,Dh]
__device__ __align__(256) __half g_k[(size_t)BATCH*NHEAD*SEQ*HEAD_DIM];   // [B,H,S,Dh]
__device__ __align__(256) __half g_v[(size_t)BATCH*NHEAD*SEQ*HEAD_DIM];   // [B,H,Dh,S] TRANSPOSED
__device__ __align__(256) __half g_ctx[(size_t)MTOK*D_MODEL];             // [B,S,D]
__device__ __align__(256) __half g_x[(size_t)MTOK*D_MODEL];               // [M][K]
__device__ __align__(256) __half g_wqkv[(size_t)3*D_MODEL*D_MODEL];       // [N][K] transposed
__device__ __align__(256) __half g_wout[(size_t)D_MODEL*D_MODEL];         // [N][K] transposed

// ---------------- helpers ---------------------------------------------------
__device__ __forceinline__ float ex2(float x) {
    float y;
    asm("ex2.approx.f32 %0, %1;" : "=f"(y) : "f"(x));
    return y;
}
__device__ __forceinline__ uint32_t sa(const void* p) {
    return (uint32_t)__cvta_generic_to_shared(p);
}
__device__ __forceinline__ void cpa16(uint32_t dst, const void* src) {
    asm volatile("cp.async.cg.shared.global [%0], [%1], 16;\n" :: "r"(dst), "l"(src));
}
#define CP_COMMIT asm volatile("cp.async.commit_group;\n" ::: "memory")
#define CP_WAIT0  asm volatile("cp.async.wait_group 0;\n" ::: "memory")

__device__ __forceinline__ uint32_t h2u(float a, float b) {
    __half2 h = __floats2half2_rn(a, b);
    return *reinterpret_cast<uint32_t*>(&h);
}

// D(16x8,f32) += A(16x16 f16,row) * B(16x8 f16,col)
__device__ __forceinline__ void mma16(float* c, const uint32_t* a, const uint32_t* b) {
    asm volatile(
        "mma.sync.aligned.m16n8k16.row.col.f32.f16.f16.f32 "
        "{%0,%1,%2,%3}, {%4,%5,%6,%7}, {%8,%9}, {%0,%1,%2,%3};\n"
        : "+f"(c[0]), "+f"(c[1]), "+f"(c[2]), "+f"(c[3])
        : "r"(a[0]), "r"(a[1]), "r"(a[2]), "r"(a[3]), "r"(b[0]), "r"(b[1]));
}

// ---------------- prep kernels ----------------------------------------------
__global__ void round_h(const float* __restrict__ src, __half* __restrict__ dst, int n4)
{
    int stride = gridDim.x * blockDim.x;
    for (int i = blockIdx.x * blockDim.x + threadIdx.x; i < n4; i += stride) {
        float4 v = reinterpret_cast<const float4*>(src)[i];
        uint2 o = make_uint2(h2u(v.x, v.y), h2u(v.z, v.w));
        reinterpret_cast<uint2*>(dst)[i] = o;
    }
}

// W[K][N] fp32 -> Wt[N][K] fp16. grid (N/32, K/32), block (32,8).
__global__ void transpose_h(const float* __restrict__ src, __half* __restrict__ dst,
                            int Kdim, int Ndim)
{
    __shared__ __half ts[32][33];
    int n0 = blockIdx.x * 32, k0 = blockIdx.y * 32;
    int tx = threadIdx.x, ty = threadIdx.y;
#pragma unroll
    for (int r = 0; r < 4; r++)
        ts[ty + 8 * r][tx] = __float2half_rn(src[(size_t)(k0 + ty + 8 * r) * Ndim + n0 + tx]);
    __syncthreads();
#pragma unroll
    for (int r = 0; r < 4; r++)
        dst[(size_t)(n0 + ty + 8 * r) * Kdim + k0 + tx] = ts[tx][ty + 8 * r];
}

// ---------------- GEMM: C[M,N] = A[M,K] @ Wt[N,K]^T + bias (fp16 MMA) -------
// 128x128 CTA tile, k-tile 64, double-buffered cp.async.
// MODE 0: scatter fp16 into g_q/g_k (and g_v TRANSPOSED). MODE 1: fp32 store.
#define GP 72                       // smem pitch in halves
#define GPB 144                     // pitch bytes
#define GTB (128 * GPB)             // 18432 B per operand tile
static const int GEMM_SMEM = 4 * GTB;   // 73728 B (2 stages x (A,W))

template<int MODE>
__global__ void __launch_bounds__(256, 2)
gemm_h(const float* __restrict__ bias, float* __restrict__ C, int N, int K)
{
    extern __shared__ __align__(256) char smem[];
    const uint32_t sb = sa(smem);
    const int m0 = blockIdx.y * 128, n0 = blockIdx.x * 128;
    const int tid  = threadIdx.x;
    const int warp = tid >> 5, lane = tid & 31;
    const int mw = warp >> 1, nw = warp & 1;      // 4 x 2 warp grid, 32x64 per warp
    const int g  = lane >> 2, qq = lane & 3;

    const __half* Ag = (MODE == 1) ? g_ctx : g_x;       // [M][K]
    const __half* Wg = (MODE == 1) ? g_wout : g_wqkv;   // [N][K]

    float acc[2][8][4];
#pragma unroll
    for (int i = 0; i < 2; i++)
#pragma unroll
        for (int j = 0; j < 8; j++)
#pragma unroll
            for (int r = 0; r < 4; r++) acc[i][j][r] = 0.f;

    const int lrow = tid >> 1;             // 128 rows, 2 threads/row
    const int lh   = (tid & 1) * 32;       // halves offset within row
    auto load_tiles = [&](int kt, int s) {
        const __half* As = Ag + (size_t)(m0 + lrow) * K + kt * 64 + lh;
        const __half* Ws = Wg + (size_t)(n0 + lrow) * K + kt * 64 + lh;
        uint32_t ab = sb + s * 2 * GTB;
        uint32_t wb = ab + GTB;
        uint32_t off = lrow * GPB + lh * 2;
#pragma unroll
        for (int j = 0; j < 4; j++) {
            cpa16(ab + off + j * 16, As + j * 8);
            cpa16(wb + off + j * 16, Ws + j * 8);
        }
        CP_COMMIT;
    };

    const int NT = K >> 6;   // k-tiles of 64
    load_tiles(0, 0);

    for (int kt = 0; kt < NT; kt++) {
        CP_WAIT0;
        __syncthreads();
        if (kt + 1 < NT) load_tiles(kt + 1, (kt + 1) & 1);

        const uint32_t* Ab = reinterpret_cast<const uint32_t*>(smem + (kt & 1) * 2 * GTB);
        const uint32_t* Wb = reinterpret_cast<const uint32_t*>(smem + (kt & 1) * 2 * GTB + GTB);

#pragma unroll
        for (int kc = 0; kc < 4; kc++) {
            uint32_t af[2][4], bf[8][2];
#pragma unroll
            for (int mt = 0; mt < 2; mt++) {
                int r = mw * 32 + mt * 16;
                int base = kc * 8 + qq;
                af[mt][0] = Ab[(r + g    ) * 36 + base    ];
                af[mt][1] = Ab[(r + g + 8) * 36 + base    ];
                af[mt][2] = Ab[(r + g    ) * 36 + base + 4];
                af[mt][3] = Ab[(r + g + 8) * 36 + base + 4];
            }
#pragma unroll
            for (int nt = 0; nt < 8; nt++) {
                int c = nw * 64 + nt * 8 + g;
                bf[nt][0] = Wb[c * 36 + kc * 8 + qq    ];
                bf[nt][1] = Wb[c * 36 + kc * 8 + qq + 4];
            }
#pragma unroll
            for (int mt = 0; mt < 2; mt++)
#pragma unroll
                for (int nt = 0; nt < 8; nt++)
                    mma16(acc[mt][nt], af[mt], bf[nt]);
        }
    }

    // epilogue
#pragma unroll
    for (int mt = 0; mt < 2; mt++) {
#pragma unroll
        for (int nt = 0; nt < 8; nt++) {
            int col = n0 + nw * 64 + nt * 8 + 2 * qq;
            float b0 = __ldg(bias + col), b1 = __ldg(bias + col + 1);
#pragma unroll
            for (int half = 0; half < 2; half++) {
                int row = m0 + mw * 32 + mt * 16 + g + half * 8;
                float v0 = acc[mt][nt][half * 2    ] + b0;
                float v1 = acc[mt][nt][half * 2 + 1] + b1;
                if (MODE == 0) {
                    int c = col >> 10;            // 0:q 1:k 2:v
                    int h = (col >> 6) & 15;
                    int d = col & 63;
                    int b = row >> 11;
                    int s = row & 2047;
                    if (c == 2) {
                        // V transposed: [B,H,Dh,S]
                        size_t vb = ((size_t)((b * NHEAD + h) * HEAD_DIM + d)) * SEQ + s;
                        g_v[vb]       = __float2half_rn(v0);
                        g_v[vb + SEQ] = __float2half_rn(v1);
                    } else {
                        size_t idx = ((size_t)((b * NHEAD + h) * SEQ + s)) * HEAD_DIM + d;
                        __half* dst = (c == 0) ? g_q : g_k;
                        __half2 hv = __floats2half2_rn(v0, v1);
                        *reinterpret_cast<__half2*>(dst + idx) = hv;
                    }
                } else {
                    *reinterpret_cast<float2*>(C + (size_t)row * N + col) =
                        make_float2(v0, v1);
                }
            }
        }
    }
}

// ---------------- flash attention (fp16 MMA) --------------------------------
// grid: (S/128, H, B); block 256 (8 warps, 16 query rows each).
// Q tile 128x64, K/V tiles 64x64, double-buffered cp.async.
#define SQ_OFF 0
#define KTB (64 * GPB)              // 9216 B
#define SK_OFF(s) (128 * GPB + (s) * KTB)
#define SV_OFF(s) (128 * GPB + 2 * KTB + (s) * KTB)
static const int ATTN_SMEM = 128 * GPB + 4 * KTB;   // 55296 B

__global__ void __launch_bounds__(256)
attn_h()
{
    extern __shared__ __align__(256) char smem[];
    const uint32_t sb = sa(smem);

    const int tid = threadIdx.x, warp = tid >> 5, lane = tid & 31;
    const int g = lane >> 2, qq = lane & 3;

    const int qt = blockIdx.x, h = blockIdx.y, b = blockIdx.z;
    const size_t head_off = ((size_t)(b * NHEAD + h)) * SEQ * HEAD_DIM;
    const __half* Qg = g_q + head_off;
    const __half* Kg = g_k + head_off;
    const __half* Vg = g_v + head_off;   // [Dh][S]

    // K/V loaders: 64 rows x 128B, 4 threads/row
    const int kvrow = tid >> 2;
    const int kvq = (tid & 3) * 16;      // halves offset
    auto load_kv = [&](int kt, int s) {
        const __half* Ks = Kg + (size_t)(kt * 64 + kvrow) * HEAD_DIM + kvq;
        const __half* Vs = Vg + (size_t)kvrow * SEQ + kt * 64 + kvq;
        uint32_t kb = sb + SK_OFF(s) + kvrow * GPB + kvq * 2;
        uint32_t vb = sb + SV_OFF(s) + kvrow * GPB + kvq * 2;
#pragma unroll
        for (int j = 0; j < 2; j++) {
            cpa16(kb + j * 16, Ks + j * 8);
            cpa16(vb + j * 16, Vs + j * 8);
        }
        CP_COMMIT;
    };

    // Q: 128 rows x 128B, 2 threads/row
    {
        const int qrow = tid >> 1;
        const int qh = (tid & 1) * 32;
        const __half* Qs = Qg + (size_t)(qt * 128 + qrow) * HEAD_DIM + qh;
        uint32_t qb = sb + SQ_OFF + qrow * GPB + qh * 2;
#pragma unroll
        for (int j = 0; j < 4; j++)
            cpa16(qb + j * 16, Qs + j * 8);
    }
    load_kv(0, 0);

    float oacc[8][4];
#pragma unroll
    for (int i = 0; i < 8; i++)
#pragma unroll
        for (int r = 0; r < 4; r++) oacc[i][r] = 0.f;
    float mrow[2] = {-1e30f, -1e30f};
    float lrow[2] = {0.f, 0.f};

    const float SCALE = 0.125f * 1.4426950408889634f;   // 1/sqrt(Dh) * log2(e)

    const int NT = SEQ / 64;
    for (int kt = 0; kt < NT; kt++) {
        CP_WAIT0;
        __syncthreads();
        if (kt + 1 < NT) load_kv(kt + 1, (kt + 1) & 1);

        const uint32_t* Qu = reinterpret_cast<const uint32_t*>(smem + SQ_OFF);
        const uint32_t* Kb = reinterpret_cast<const uint32_t*>(smem + SK_OFF(kt & 1));
        const uint32_t* Vb = reinterpret_cast<const uint32_t*>(smem + SV_OFF(kt & 1));

        // S = Q K^T  (16 x 64 per warp)
        float sacc[8][4];
#pragma unroll
        for (int i = 0; i < 8; i++)
#pragma unroll
            for (int r = 0; r < 4; r++) sacc[i][r] = 0.f;

#pragma unroll
        for (int kc = 0; kc < 4; kc++) {
            uint32_t af[4];
            int r = warp * 16;
            int base = kc * 8 + qq;
            af[0] = Qu[(r + g    ) * 36 + base    ];
            af[1] = Qu[(r + g + 8) * 36 + base    ];
            af[2] = Qu[(r + g    ) * 36 + base + 4];
            af[3] = Qu[(r + g + 8) * 36 + base + 4];
#pragma unroll
            for (int nt = 0; nt < 8; nt++) {
                uint32_t bf[2] = { Kb[(nt * 8 + g) * 36 + base    ],
                                   Kb[(nt * 8 + g) * 36 + base + 4] };
                mma16(sacc[nt], af, bf);
            }
        }

#pragma unroll
        for (int nt = 0; nt < 8; nt++)
#pragma unroll
            for (int r = 0; r < 4; r++) sacc[nt][r] *= SCALE;

        // online softmax in log2 domain (two rows per thread: g and g+8)
#pragma unroll
        for (int rr = 0; rr < 2; rr++) {
            float mloc = -1e30f;
#pragma unroll
            for (int nt = 0; nt < 8; nt++)
                mloc = fmaxf(mloc, fmaxf(sacc[nt][rr * 2], sacc[nt][rr * 2 + 1]));
            mloc = fmaxf(mloc, __shfl_xor_sync(0xffffffffu, mloc, 1));
            mloc = fmaxf(mloc, __shfl_xor_sync(0xffffffffu, mloc, 2));
            float mnew  = fmaxf(mrow[rr], mloc);
            float alpha = ex2(mrow[rr] - mnew);
            mrow[rr] = mnew;
            float lsum = 0.f;
#pragma unroll
            for (int nt = 0; nt < 8; nt++) {
                float p0 = ex2(sacc[nt][rr * 2]     - mnew);
                float p1 = ex2(sacc[nt][rr * 2 + 1] - mnew);
                sacc[nt][rr * 2] = p0; sacc[nt][rr * 2 + 1] = p1;
                lsum += p0 + p1;
            }
            lsum += __shfl_xor_sync(0xffffffffu, lsum, 1);
            lsum += __shfl_xor_sync(0xffffffffu, lsum, 2);
            lrow[rr] = lrow[rr] * alpha + lsum;
#pragma unroll
            for (int dt = 0; dt < 8; dt++) {
                oacc[dt][rr * 2]     *= alpha;
                oacc[dt][rr * 2 + 1] *= alpha;
            }
        }

        // O += P @ V — P converted in registers (C-frag pair == A-frag of k16)
#pragma unroll
        for (int jc = 0; jc < 4; jc++) {
            uint32_t af[4];
            af[0] = h2u(sacc[2 * jc    ][0], sacc[2 * jc    ][1]);
            af[1] = h2u(sacc[2 * jc    ][2], sacc[2 * jc    ][3]);
            af[2] = h2u(sacc[2 * jc + 1][0], sacc[2 * jc + 1][1]);
            af[3] = h2u(sacc[2 * jc + 1][2], sacc[2 * jc + 1][3]);
#pragma unroll
            for (int dt = 0; dt < 8; dt++) {
                uint32_t bf[2] = { Vb[(dt * 8 + g) * 36 + jc * 8 + qq    ],
                                   Vb[(dt * 8 + g) * 36 + jc * 8 + qq + 4] };
                mma16(oacc[dt], af, bf);
            }
        }
    }

    // normalize; write ctx fp16 in [B,S,D] layout
#pragma unroll
    for (int rr = 0; rr < 2; rr++) {
        float inv = 1.f / lrow[rr];
        int s = qt * 128 + warp * 16 + g + rr * 8;
        size_t base = ((size_t)(b * SEQ + s)) * D_MODEL;
#pragma unroll
        for (int dt = 0; dt < 8; dt++) {
            int d0 = h * HEAD_DIM + dt * 8 + 2 * qq;
            __half2 hv = __floats2half2_rn(oacc[dt][rr * 2] * inv,
                                           oacc[dt][rr * 2 + 1] * inv);
            *reinterpret_cast<__half2*>(g_ctx + base + d0) = hv;
        }
    }
}

// ---------------- launch -----------------------------------------------------
extern "C" void kernel_launch(void* const* d_in, const int* in_sizes, int n_in,
                              void* d_out, int out_size)
{
    const float* x     = (const float*)d_in[0];
    const float* W_qkv = (const float*)d_in[1];
    const float* b_qkv = (const float*)d_in[2];
    const float* W_out = (const float*)d_in[3];
    const float* b_out = (const float*)d_in[4];
    float* out = (float*)d_out;

    cudaFuncSetAttribute(gemm_h<0>, cudaFuncAttributeMaxDynamicSharedMemorySize, GEMM_SMEM);
    cudaFuncSetAttribute(gemm_h<1>, cudaFuncAttributeMaxDynamicSharedMemorySize, GEMM_SMEM);
    cudaFuncSetAttribute(attn_h,    cudaFuncAttributeMaxDynamicSharedMemorySize, ATTN_SMEM);

    __half* gx; __half* gwq; __half* gwo;
    cudaGetSymbolAddress((void**)&gx,  g_x);
    cudaGetSymbolAddress((void**)&gwq, g_wqkv);
    cudaGetSymbolAddress((void**)&gwo, g_wout);

    // 0) prep: round x to fp16; transpose+round weights to [N][K] fp16
    round_h<<<2048, 256>>>(x, gx, MTOK * D_MODEL / 4);
    transpose_h<<<dim3(3 * D_MODEL / 32, D_MODEL / 32), dim3(32, 8)>>>(
        W_qkv, gwq, D_MODEL, 3 * D_MODEL);
    transpose_h<<<dim3(D_MODEL / 32, D_MODEL / 32), dim3(32, 8)>>>(
        W_out, gwo, D_MODEL, D_MODEL);

    // 1) QKV projection -> g_q/g_k ([B,H,S,Dh]), g_v ([B,H,Dh,S])
    gemm_h<0><<<dim3(3 * D_MODEL / 128, MTOK / 128), 256, GEMM_SMEM>>>(
        b_qkv, nullptr, 3 * D_MODEL, D_MODEL);

    // 2) flash attention -> ctx [B,S,D] fp16
    attn_h<<<dim3(SEQ / 128, NHEAD, BATCH), 256, ATTN_SMEM>>>();

    // 3) output projection (final fp32)
    gemm_h<1><<<dim3(D_MODEL / 128, MTOK / 128), 256, GEMM_SMEM>>>(
        b_out, out, D_MODEL, D_MODEL);
}

// round 9
// speedup vs baseline: 2.2526x; 1.0741x over previous
#include <cuda_runtime.h>
#include <cuda_fp16.h>
#include <cstdint>

#define D_MODEL 1024
#define NHEAD 16
#define HEAD_DIM 64
#define BATCH 4
#define SEQ 2048
#define MTOK (BATCH*SEQ)   // 8192

// ---------------- scratch (static device globals: allocation-free) ----------
__device__ __align__(256) __half g_q[(size_t)BATCH*NHEAD*SEQ*HEAD_DIM];   // [B,H,S,Dh]
__device__ __align__(256) __half g_k[(size_t)BATCH*NHEAD*SEQ*HEAD_DIM];   // [B,H,S,Dh]
__device__ __align__(256) __half g_v[(size_t)BATCH*NHEAD*SEQ*HEAD_DIM];   // [B,H,Dh,S] TRANSPOSED
__device__ __align__(256) __half g_ctx[(size_t)MTOK*D_MODEL];             // [B,S,D]
__device__ __align__(256) __half g_x[(size_t)MTOK*D_MODEL];               // [M][K]
__device__ __align__(256) __half g_wqkv[(size_t)3*D_MODEL*D_MODEL];       // [N][K] transposed
__device__ __align__(256) __half g_wout[(size_t)D_MODEL*D_MODEL];         // [N][K] transposed

// ---------------- helpers ---------------------------------------------------
__device__ __forceinline__ float ex2(float x) {
    float y;
    asm("ex2.approx.f32 %0, %1;" : "=f"(y) : "f"(x));
    return y;
}
__device__ __forceinline__ uint32_t sa(const void* p) {
    return (uint32_t)__cvta_generic_to_shared(p);
}
__device__ __forceinline__ void cpa16(uint32_t dst, const void* src) {
    asm volatile("cp.async.cg.shared.global [%0], [%1], 16;\n" :: "r"(dst), "l"(src));
}
#define CP_COMMIT asm volatile("cp.async.commit_group;\n" ::: "memory")
#define CP_WAIT1  asm volatile("cp.async.wait_group 1;\n" ::: "memory")

__device__ __forceinline__ uint32_t h2u(float a, float b) {
    __half2 h = __floats2half2_rn(a, b);
    return *reinterpret_cast<uint32_t*>(&h);
}
__device__ __forceinline__ void ldsm4(uint32_t* r, uint32_t addr) {
    asm volatile("ldmatrix.sync.aligned.m8n8.x4.shared.b16 {%0,%1,%2,%3}, [%4];"
                 : "=r"(r[0]), "=r"(r[1]), "=r"(r[2]), "=r"(r[3]) : "r"(addr));
}

// D(16x8,f32) += A(16x16 f16,row) * B(16x8 f16,col)
__device__ __forceinline__ void mma16(float* c, const uint32_t* a, const uint32_t* b) {
    asm volatile(
        "mma.sync.aligned.m16n8k16.row.col.f32.f16.f16.f32 "
        "{%0,%1,%2,%3}, {%4,%5,%6,%7}, {%8,%9}, {%0,%1,%2,%3};\n"
        : "+f"(c[0]), "+f"(c[1]), "+f"(c[2]), "+f"(c[3])
        : "r"(a[0]), "r"(a[1]), "r"(a[2]), "r"(a[3]), "r"(b[0]), "r"(b[1]));
}

// ---------------- prep kernels ----------------------------------------------
__global__ void round_h(const float* __restrict__ src, __half* __restrict__ dst, int n4)
{
    int stride = gridDim.x * blockDim.x;
    for (int i = blockIdx.x * blockDim.x + threadIdx.x; i < n4; i += stride) {
        float4 v = reinterpret_cast<const float4*>(src)[i];
        uint2 o = make_uint2(h2u(v.x, v.y), h2u(v.z, v.w));
        reinterpret_cast<uint2*>(dst)[i] = o;
    }
}

// W[K][N] fp32 -> Wt[N][K] fp16. grid (N/32, K/32), block (32,8).
__global__ void transpose_h(const float* __restrict__ src, __half* __restrict__ dst,
                            int Kdim, int Ndim)
{
    __shared__ __half ts[32][33];
    int n0 = blockIdx.x * 32, k0 = blockIdx.y * 32;
    int tx = threadIdx.x, ty = threadIdx.y;
#pragma unroll
    for (int r = 0; r < 4; r++)
        ts[ty + 8 * r][tx] = __float2half_rn(src[(size_t)(k0 + ty + 8 * r) * Ndim + n0 + tx]);
    __syncthreads();
#pragma unroll
    for (int r = 0; r < 4; r++)
        dst[(size_t)(n0 + ty + 8 * r) * Kdim + k0 + tx] = ts[tx][ty + 8 * r];
}

// ---------------- GEMM: C[M,N] = A[M,K] @ Wt[N,K]^T + bias (fp16 MMA) -------
// 128x128 CTA tile, k-tile 64, 3-stage cp.async pipeline, ldmatrix fragments.
#define GPB 144                     // smem pitch bytes (72 halves)
#define GTB (128 * GPB)             // 18432 B per operand tile
static const int GEMM_SMEM = 6 * GTB;   // 110592 B (3 stages x (A,W))

template<int MODE>
__global__ void __launch_bounds__(256, 2)
gemm_h(const float* __restrict__ bias, float* __restrict__ C, int N, int K)
{
    extern __shared__ __align__(256) char smem[];
    const uint32_t sb = sa(smem);
    const int m0 = blockIdx.y * 128, n0 = blockIdx.x * 128;
    const int tid  = threadIdx.x;
    const int warp = tid >> 5, lane = tid & 31;
    const int mw = warp >> 1, nw = warp & 1;      // 4 x 2 warp grid, 32x64 per warp
    const int g  = lane >> 2, qq = lane & 3;

    const __half* Ag = (MODE == 1) ? g_ctx : g_x;       // [M][K]
    const __half* Wg = (MODE == 1) ? g_wout : g_wqkv;   // [N][K]

    float acc[2][8][4];
#pragma unroll
    for (int i = 0; i < 2; i++)
#pragma unroll
        for (int j = 0; j < 8; j++)
#pragma unroll
            for (int r = 0; r < 4; r++) acc[i][j][r] = 0.f;

    const int lrow = tid >> 1;             // 128 rows, 2 threads/row
    const int lh   = (tid & 1) * 32;       // halves offset within row
    auto load_tiles = [&](int kt, int s) {
        const __half* As = Ag + (size_t)(m0 + lrow) * K + kt * 64 + lh;
        const __half* Ws = Wg + (size_t)(n0 + lrow) * K + kt * 64 + lh;
        uint32_t ab = sb + s * 2 * GTB;
        uint32_t wb = ab + GTB;
        uint32_t off = lrow * GPB + lh * 2;
#pragma unroll
        for (int j = 0; j < 4; j++) {
            cpa16(ab + off + j * 16, As + j * 8);
            cpa16(wb + off + j * 16, Ws + j * 8);
        }
        CP_COMMIT;
    };

    // per-lane ldmatrix byte offsets within a tile
    const uint32_t aoff = (uint32_t)((lane & 15) * GPB + (lane >> 4) * 16);
    const uint32_t boff = (uint32_t)(((lane & 7) + ((lane >> 4) << 3)) * GPB
                                     + ((lane >> 3) & 1) * 16);

    const int NT = K >> 6;   // k-tiles of 64
    load_tiles(0, 0);
    load_tiles(1, 1);

    for (int kt = 0; kt < NT; kt++) {
        CP_WAIT1;
        __syncthreads();
        if (kt + 2 < NT) load_tiles(kt + 2, (kt + 2) % 3);

        const int s = kt % 3;
        const uint32_t ab = sb + s * 2 * GTB;
        const uint32_t wb = ab + GTB;

#pragma unroll
        for (int kc = 0; kc < 4; kc++) {
            uint32_t af[2][4], bf[8][2];
#pragma unroll
            for (int mt = 0; mt < 2; mt++)
                ldsm4(af[mt], ab + (mw * 32 + mt * 16) * GPB + aoff + kc * 32);
#pragma unroll
            for (int p = 0; p < 4; p++) {
                uint32_t bq[4];
                ldsm4(bq, wb + (nw * 64 + p * 16) * GPB + boff + kc * 32);
                bf[2 * p    ][0] = bq[0]; bf[2 * p    ][1] = bq[1];
                bf[2 * p + 1][0] = bq[2]; bf[2 * p + 1][1] = bq[3];
            }
#pragma unroll
            for (int mt = 0; mt < 2; mt++)
#pragma unroll
                for (int nt = 0; nt < 8; nt++)
                    mma16(acc[mt][nt], af[mt], bf[nt]);
        }
    }

    // epilogue
#pragma unroll
    for (int mt = 0; mt < 2; mt++) {
#pragma unroll
        for (int nt = 0; nt < 8; nt++) {
            int col = n0 + nw * 64 + nt * 8 + 2 * qq;
            float b0 = __ldg(bias + col), b1 = __ldg(bias + col + 1);
#pragma unroll
            for (int half = 0; half < 2; half++) {
                int row = m0 + mw * 32 + mt * 16 + g + half * 8;
                float v0 = acc[mt][nt][half * 2    ] + b0;
                float v1 = acc[mt][nt][half * 2 + 1] + b1;
                if (MODE == 0) {
                    int c = col >> 10;            // 0:q 1:k 2:v
                    int h = (col >> 6) & 15;
                    int d = col & 63;
                    int b = row >> 11;
                    int s = row & 2047;
                    if (c == 2) {
                        // V transposed: [B,H,Dh,S]
                        size_t vb = ((size_t)((b * NHEAD + h) * HEAD_DIM + d)) * SEQ + s;
                        g_v[vb]       = __float2half_rn(v0);
                        g_v[vb + SEQ] = __float2half_rn(v1);
                    } else {
                        size_t idx = ((size_t)((b * NHEAD + h) * SEQ + s)) * HEAD_DIM + d;
                        __half* dst = (c == 0) ? g_q : g_k;
                        __half2 hv = __floats2half2_rn(v0, v1);
                        *reinterpret_cast<__half2*>(dst + idx) = hv;
                    }
                } else {
                    *reinterpret_cast<float2*>(C + (size_t)row * N + col) =
                        make_float2(v0, v1);
                }
            }
        }
    }
}

// ---------------- flash attention (fp16 MMA, ldmatrix, 3-stage) -------------
// grid: (S/128, H, B); block 256 (8 warps, 16 query rows each).
#define QTB (128 * GPB)             // 18432 B
#define KTB (64 * GPB)              // 9216 B
#define SK_OFF(s) (QTB + (s) * KTB)
#define SV_OFF(s) (QTB + 3 * KTB + (s) * KTB)
static const int ATTN_SMEM = QTB + 6 * KTB;   // 73728 B

__global__ void __launch_bounds__(256, 2)
attn_h()
{
    extern __shared__ __align__(256) char smem[];
    const uint32_t sb = sa(smem);

    const int tid = threadIdx.x, warp = tid >> 5, lane = tid & 31;

    const int qt = blockIdx.x, h = blockIdx.y, b = blockIdx.z;
    const size_t head_off = ((size_t)(b * NHEAD + h)) * SEQ * HEAD_DIM;
    const __half* Qg = g_q + head_off;
    const __half* Kg = g_k + head_off;
    const __half* Vg = g_v + head_off;   // [Dh][S]

    // K/V loaders: 64 rows x 128B, 4 threads/row
    const int kvrow = tid >> 2;
    const int kvq = (tid & 3) * 16;      // halves offset
    auto load_kv = [&](int kt, int s) {
        const __half* Ks = Kg + (size_t)(kt * 64 + kvrow) * HEAD_DIM + kvq;
        const __half* Vs = Vg + (size_t)kvrow * SEQ + kt * 64 + kvq;
        uint32_t kb = sb + SK_OFF(s) + kvrow * GPB + kvq * 2;
        uint32_t vb = sb + SV_OFF(s) + kvrow * GPB + kvq * 2;
#pragma unroll
        for (int j = 0; j < 2; j++) {
            cpa16(kb + j * 16, Ks + j * 8);
            cpa16(vb + j * 16, Vs + j * 8);
        }
        CP_COMMIT;
    };

    // Q: 128 rows x 128B, 2 threads/row (committed with kv tile 0)
    {
        const int qrow = tid >> 1;
        const int qh = (tid & 1) * 32;
        const __half* Qs = Qg + (size_t)(qt * 128 + qrow) * HEAD_DIM + qh;
        uint32_t qb = sb + qrow * GPB + qh * 2;
#pragma unroll
        for (int j = 0; j < 4; j++)
            cpa16(qb + j * 16, Qs + j * 8);
    }
    load_kv(0, 0);
    load_kv(1, 1);

    // ldmatrix per-lane offsets
    const uint32_t aoff = (uint32_t)((lane & 15) * GPB + (lane >> 4) * 16);
    const uint32_t boff = (uint32_t)(((lane & 7) + ((lane >> 4) << 3)) * GPB
                                     + ((lane >> 3) & 1) * 16);

    float oacc[8][4];
#pragma unroll
    for (int i = 0; i < 8; i++)
#pragma unroll
        for (int r = 0; r < 4; r++) oacc[i][r] = 0.f;
    float mrow[2] = {-1e30f, -1e30f};
    float lrow[2] = {0.f, 0.f};

    const float SCALE = 0.125f * 1.4426950408889634f;   // 1/sqrt(Dh) * log2(e)

    // hoist Q fragments (k-tile invariant): 4 kc x 4 regs
    uint32_t qf[4][4];
    bool qloaded = false;

    const int NT = SEQ / 64;
    for (int kt = 0; kt < NT; kt++) {
        CP_WAIT1;
        __syncthreads();
        if (kt + 2 < NT) load_kv(kt + 2, (kt + 2) % 3);

        if (!qloaded) {
#pragma unroll
            for (int kc = 0; kc < 4; kc++)
                ldsm4(qf[kc], sb + (warp * 16) * GPB + aoff + kc * 32);
            qloaded = true;
        }

        const int s = kt % 3;
        const uint32_t kb = sb + SK_OFF(s);
        const uint32_t vb = sb + SV_OFF(s);

        // S = Q K^T  (16 x 64 per warp)
        float sacc[8][4];
#pragma unroll
        for (int i = 0; i < 8; i++)
#pragma unroll
            for (int r = 0; r < 4; r++) sacc[i][r] = 0.f;

#pragma unroll
        for (int kc = 0; kc < 4; kc++) {
#pragma unroll
            for (int p = 0; p < 4; p++) {
                uint32_t bq[4];
                ldsm4(bq, kb + (p * 16) * GPB + boff + kc * 32);
                mma16(sacc[2 * p    ], qf[kc], bq);
                mma16(sacc[2 * p + 1], qf[kc], bq + 2);
            }
        }

#pragma unroll
        for (int nt = 0; nt < 8; nt++)
#pragma unroll
            for (int r = 0; r < 4; r++) sacc[nt][r] *= SCALE;

        // online softmax in log2 domain (two rows per thread: g and g+8)
#pragma unroll
        for (int rr = 0; rr < 2; rr++) {
            float mloc = -1e30f;
#pragma unroll
            for (int nt = 0; nt < 8; nt++)
                mloc = fmaxf(mloc, fmaxf(sacc[nt][rr * 2], sacc[nt][rr * 2 + 1]));
            mloc = fmaxf(mloc, __shfl_xor_sync(0xffffffffu, mloc, 1));
            mloc = fmaxf(mloc, __shfl_xor_sync(0xffffffffu, mloc, 2));
            float mnew  = fmaxf(mrow[rr], mloc);
            float alpha = ex2(mrow[rr] - mnew);
            mrow[rr] = mnew;
            float lsum = 0.f;
#pragma unroll
            for (int nt = 0; nt < 8; nt++) {
                float p0 = ex2(sacc[nt][rr * 2]     - mnew);
                float p1 = ex2(sacc[nt][rr * 2 + 1] - mnew);
                sacc[nt][rr * 2] = p0; sacc[nt][rr * 2 + 1] = p1;
                lsum += p0 + p1;
            }
            lsum += __shfl_xor_sync(0xffffffffu, lsum, 1);
            lsum += __shfl_xor_sync(0xffffffffu, lsum, 2);
            lrow[rr] = lrow[rr] * alpha + lsum;
#pragma unroll
            for (int dt = 0; dt < 8; dt++) {
                oacc[dt][rr * 2]     *= alpha;
                oacc[dt][rr * 2 + 1] *= alpha;
            }
        }

        // O += P @ V — P converted in registers (C-frag pair == A-frag of k16)
#pragma unroll
        for (int jc = 0; jc < 4; jc++) {
            uint32_t af[4];
            af[0] = h2u(sacc[2 * jc    ][0], sacc[2 * jc    ][1]);
            af[1] = h2u(sacc[2 * jc    ][2], sacc[2 * jc    ][3]);
            af[2] = h2u(sacc[2 * jc + 1][0], sacc[2 * jc + 1][1]);
            af[3] = h2u(sacc[2 * jc + 1][2], sacc[2 * jc + 1][3]);
#pragma unroll
            for (int p = 0; p < 4; p++) {
                uint32_t bq[4];
                ldsm4(bq, vb + (p * 16) * GPB + boff + jc * 32);
                mma16(oacc[2 * p    ], af, bq);
                mma16(oacc[2 * p + 1], af, bq + 2);
            }
        }
    }

    // normalize; write ctx fp16 in [B,S,D] layout
    const int g = lane >> 2, qq = lane & 3;
#pragma unroll
    for (int rr = 0; rr < 2; rr++) {
        float inv = 1.f / lrow[rr];
        int s = qt * 128 + warp * 16 + g + rr * 8;
        size_t base = ((size_t)(b * SEQ + s)) * D_MODEL;
#pragma unroll
        for (int dt = 0; dt < 8; dt++) {
            int d0 = h * HEAD_DIM + dt * 8 + 2 * qq;
            __half2 hv = __floats2half2_rn(oacc[dt][rr * 2] * inv,
                                           oacc[dt][rr * 2 + 1] * inv);
            *reinterpret_cast<__half2*>(g_ctx + base + d0) = hv;
        }
    }
}

// ---------------- launch -----------------------------------------------------
extern "C" void kernel_launch(void* const* d_in, const int* in_sizes, int n_in,
                              void* d_out, int out_size)
{
    const float* x     = (const float*)d_in[0];
    const float* W_qkv = (const float*)d_in[1];
    const float* b_qkv = (const float*)d_in[2];
    const float* W_out = (const float*)d_in[3];
    const float* b_out = (const float*)d_in[4];
    float* out = (float*)d_out;

    cudaFuncSetAttribute(gemm_h<0>, cudaFuncAttributeMaxDynamicSharedMemorySize, GEMM_SMEM);
    cudaFuncSetAttribute(gemm_h<1>, cudaFuncAttributeMaxDynamicSharedMemorySize, GEMM_SMEM);
    cudaFuncSetAttribute(attn_h,    cudaFuncAttributeMaxDynamicSharedMemorySize, ATTN_SMEM);

    __half* gx; __half* gwq; __half* gwo;
    cudaGetSymbolAddress((void**)&gx,  g_x);
    cudaGetSymbolAddress((void**)&gwq, g_wqkv);
    cudaGetSymbolAddress((void**)&gwo, g_wout);

    // 0) prep: round x to fp16; transpose+round weights to [N][K] fp16
    round_h<<<2048, 256>>>(x, gx, MTOK * D_MODEL / 4);
    transpose_h<<<dim3(3 * D_MODEL / 32, D_MODEL / 32), dim3(32, 8)>>>(
        W_qkv, gwq, D_MODEL, 3 * D_MODEL);
    transpose_h<<<dim3(D_MODEL / 32, D_MODEL / 32), dim3(32, 8)>>>(
        W_out, gwo, D_MODEL, D_MODEL);

    // 1) QKV projection -> g_q/g_k ([B,H,S,Dh]), g_v ([B,H,Dh,S])
    gemm_h<0><<<dim3(3 * D_MODEL / 128, MTOK / 128), 256, GEMM_SMEM>>>(
        b_qkv, nullptr, 3 * D_MODEL, D_MODEL);

    // 2) flash attention -> ctx [B,S,D] fp16
    attn_h<<<dim3(SEQ / 128, NHEAD, BATCH), 256, ATTN_SMEM>>>();

    // 3) output projection (final fp32)
    gemm_h<1><<<dim3(D_MODEL / 128, MTOK / 128), 256, GEMM_SMEM>>>(
        b_out, out, D_MODEL, D_MODEL);
}

// round 10
// speedup vs baseline: 2.3979x; 1.0645x over previous
#include <cuda_runtime.h>
#include <cuda_fp16.h>
#include <cstdint>

#define D_MODEL 1024
#define NHEAD 16
#define HEAD_DIM 64
#define BATCH 4
#define SEQ 2048
#define MTOK (BATCH*SEQ)   // 8192

// ---------------- scratch (static device globals: allocation-free) ----------
__device__ __align__(256) __half g_q[(size_t)BATCH*NHEAD*SEQ*HEAD_DIM];   // [B,H,S,Dh]
__device__ __align__(256) __half g_k[(size_t)BATCH*NHEAD*SEQ*HEAD_DIM];   // [B,H,S,Dh]
__device__ __align__(256) __half g_v[(size_t)BATCH*NHEAD*SEQ*HEAD_DIM];   // [B,H,Dh,S] TRANSPOSED
__device__ __align__(256) __half g_ctx[(size_t)MTOK*D_MODEL];             // [B,S,D]
__device__ __align__(256) __half g_x[(size_t)MTOK*D_MODEL];               // [M][K]
__device__ __align__(256) __half g_wqkv[(size_t)3*D_MODEL*D_MODEL];       // [N][K] transposed
__device__ __align__(256) __half g_wout[(size_t)D_MODEL*D_MODEL];         // [N][K] transposed

// ---------------- helpers ---------------------------------------------------
__device__ __forceinline__ float ex2(float x) {
    float y;
    asm("ex2.approx.f32 %0, %1;" : "=f"(y) : "f"(x));
    return y;
}
__device__ __forceinline__ uint32_t sa(const void* p) {
    return (uint32_t)__cvta_generic_to_shared(p);
}
__device__ __forceinline__ void cpa16(uint32_t dst, const void* src) {
    asm volatile("cp.async.cg.shared.global [%0], [%1], 16;\n" :: "r"(dst), "l"(src));
}
#define CP_COMMIT asm volatile("cp.async.commit_group;\n" ::: "memory")
#define CP_WAIT1  asm volatile("cp.async.wait_group 1;\n" ::: "memory")

__device__ __forceinline__ uint32_t h2u(float a, float b) {
    __half2 h = __floats2half2_rn(a, b);
    return *reinterpret_cast<uint32_t*>(&h);
}
__device__ __forceinline__ void ldsm4(uint32_t* r, uint32_t addr) {
    asm volatile("ldmatrix.sync.aligned.m8n8.x4.shared.b16 {%0,%1,%2,%3}, [%4];"
                 : "=r"(r[0]), "=r"(r[1]), "=r"(r[2]), "=r"(r[3]) : "r"(addr));
}

// D(16x8,f32) += A(16x16 f16,row) * B(16x8 f16,col)
__device__ __forceinline__ void mma16(float* c, const uint32_t* a, const uint32_t* b) {
    asm volatile(
        "mma.sync.aligned.m16n8k16.row.col.f32.f16.f16.f32 "
        "{%0,%1,%2,%3}, {%4,%5,%6,%7}, {%8,%9}, {%0,%1,%2,%3};\n"
        : "+f"(c[0]), "+f"(c[1]), "+f"(c[2]), "+f"(c[3])
        : "r"(a[0]), "r"(a[1]), "r"(a[2]), "r"(a[3]), "r"(b[0]), "r"(b[1]));
}

// ---------------- prep kernels ----------------------------------------------
__global__ void round_h(const float* __restrict__ src, __half* __restrict__ dst, int n4)
{
    int stride = gridDim.x * blockDim.x;
    for (int i = blockIdx.x * blockDim.x + threadIdx.x; i < n4; i += stride) {
        float4 v = reinterpret_cast<const float4*>(src)[i];
        uint2 o = make_uint2(h2u(v.x, v.y), h2u(v.z, v.w));
        reinterpret_cast<uint2*>(dst)[i] = o;
    }
}

// W[K][N] fp32 -> Wt[N][K] fp16. grid (N/32, K/32), block (32,8).
__global__ void transpose_h(const float* __restrict__ src, __half* __restrict__ dst,
                            int Kdim, int Ndim)
{
    __shared__ __half ts[32][33];
    int n0 = blockIdx.x * 32, k0 = blockIdx.y * 32;
    int tx = threadIdx.x, ty = threadIdx.y;
#pragma unroll
    for (int r = 0; r < 4; r++)
        ts[ty + 8 * r][tx] = __float2half_rn(src[(size_t)(k0 + ty + 8 * r) * Ndim + n0 + tx]);
    __syncthreads();
#pragma unroll
    for (int r = 0; r < 4; r++)
        dst[(size_t)(n0 + ty + 8 * r) * Kdim + k0 + tx] = ts[tx][ty + 8 * r];
}

// ---------------- GEMM: C[M,N] = A[M,K] @ Wt[N,K]^T + bias (fp16 MMA) -------
// 128x128 CTA tile, k-tile 64, 3-stage cp.async, register-double-buffered
// ldmatrix fragments (software pipeline: frag loads lead MMAs by one kc).
#define GPB 144                     // smem pitch bytes (72 halves)
#define GTB (128 * GPB)             // 18432 B per operand tile
static const int GEMM_SMEM = 6 * GTB;   // 110592 B (3 stages x (A,W))

// load fragments for one kc chunk: A 2x ldsm.x4, W 4x ldsm.x4
#define G_LOAD_FRAGS(AF, BF, ABASE, WBASE, KC) do {                            \
    ldsm4(AF[0], (ABASE) + (mw * 32     ) * GPB + aoff + (KC) * 32);           \
    ldsm4(AF[1], (ABASE) + (mw * 32 + 16) * GPB + aoff + (KC) * 32);           \
    ldsm4(BF[0], (WBASE) + (nw * 64     ) * GPB + boff + (KC) * 32);           \
    ldsm4(BF[1], (WBASE) + (nw * 64 + 16) * GPB + boff + (KC) * 32);           \
    ldsm4(BF[2], (WBASE) + (nw * 64 + 32) * GPB + boff + (KC) * 32);           \
    ldsm4(BF[3], (WBASE) + (nw * 64 + 48) * GPB + boff + (KC) * 32);           \
} while (0)

#define G_MMA_ALL(AF, BF) do {                                                 \
    _Pragma("unroll")                                                          \
    for (int mt = 0; mt < 2; mt++) {                                           \
        _Pragma("unroll")                                                      \
        for (int p = 0; p < 4; p++) {                                          \
            mma16(acc[mt][2 * p    ], AF[mt], &BF[p][0]);                      \
            mma16(acc[mt][2 * p + 1], AF[mt], &BF[p][2]);                      \
        }                                                                      \
    }                                                                          \
} while (0)

template<int MODE>
__global__ void __launch_bounds__(256, 2)
gemm_h(const float* __restrict__ bias, float* __restrict__ C, int N, int K)
{
    extern __shared__ __align__(256) char smem[];
    const uint32_t sb = sa(smem);
    const int m0 = blockIdx.y * 128, n0 = blockIdx.x * 128;
    const int tid  = threadIdx.x;
    const int warp = tid >> 5, lane = tid & 31;
    const int mw = warp >> 1, nw = warp & 1;      // 4 x 2 warp grid, 32x64 per warp
    const int g  = lane >> 2, qq = lane & 3;

    const __half* Ag = (MODE == 1) ? g_ctx : g_x;       // [M][K]
    const __half* Wg = (MODE == 1) ? g_wout : g_wqkv;   // [N][K]

    float acc[2][8][4];
#pragma unroll
    for (int i = 0; i < 2; i++)
#pragma unroll
        for (int j = 0; j < 8; j++)
#pragma unroll
            for (int r = 0; r < 4; r++) acc[i][j][r] = 0.f;

    const int lrow = tid >> 1;             // 128 rows, 2 threads/row
    const int lh   = (tid & 1) * 32;       // halves offset within row
    auto load_tiles = [&](int kt, int s) {
        const __half* As = Ag + (size_t)(m0 + lrow) * K + kt * 64 + lh;
        const __half* Ws = Wg + (size_t)(n0 + lrow) * K + kt * 64 + lh;
        uint32_t ab = sb + s * 2 * GTB;
        uint32_t wb = ab + GTB;
        uint32_t off = lrow * GPB + lh * 2;
#pragma unroll
        for (int j = 0; j < 4; j++) {
            cpa16(ab + off + j * 16, As + j * 8);
            cpa16(wb + off + j * 16, Ws + j * 8);
        }
        CP_COMMIT;
    };

    // per-lane ldmatrix byte offsets within a tile
    const uint32_t aoff = (uint32_t)((lane & 15) * GPB + (lane >> 4) * 16);
    const uint32_t boff = (uint32_t)(((lane & 7) + ((lane >> 4) << 3)) * GPB
                                     + ((lane >> 3) & 1) * 16);

    uint32_t af0[2][4], bf0[4][4], af1[2][4], bf1[4][4];

    const int NT = K >> 6;   // k-tiles of 64
    load_tiles(0, 0);
    load_tiles(1, 1);
    CP_WAIT1;
    __syncthreads();
    G_LOAD_FRAGS(af0, bf0, sb, sb + GTB, 0);

    for (int kt = 0; kt < NT; kt++) {
        const int s = kt % 3;
        const uint32_t cab = sb + s * 2 * GTB;
        const uint32_t cwb = cab + GTB;

        G_LOAD_FRAGS(af1, bf1, cab, cwb, 1);
        if (kt + 2 < NT) load_tiles(kt + 2, (kt + 2) % 3);
        G_MMA_ALL(af0, bf0);

        G_LOAD_FRAGS(af0, bf0, cab, cwb, 2);
        G_MMA_ALL(af1, bf1);

        G_LOAD_FRAGS(af1, bf1, cab, cwb, 3);
        G_MMA_ALL(af0, bf0);

        if (kt + 1 < NT) {
            CP_WAIT1;
            __syncthreads();
            const uint32_t nab = sb + ((kt + 1) % 3) * 2 * GTB;
            G_LOAD_FRAGS(af0, bf0, nab, nab + GTB, 0);
        }
        G_MMA_ALL(af1, bf1);
    }

    // epilogue
#pragma unroll
    for (int mt = 0; mt < 2; mt++) {
#pragma unroll
        for (int nt = 0; nt < 8; nt++) {
            int col = n0 + nw * 64 + nt * 8 + 2 * qq;
            float b0 = __ldg(bias + col), b1 = __ldg(bias + col + 1);
#pragma unroll
            for (int half = 0; half < 2; half++) {
                int row = m0 + mw * 32 + mt * 16 + g + half * 8;
                float v0 = acc[mt][nt][half * 2    ] + b0;
                float v1 = acc[mt][nt][half * 2 + 1] + b1;
                if (MODE == 0) {
                    int c = col >> 10;            // 0:q 1:k 2:v
                    int h = (col >> 6) & 15;
                    int d = col & 63;
                    int b = row >> 11;
                    int s = row & 2047;
                    if (c == 2) {
                        // V transposed: [B,H,Dh,S]
                        size_t vb = ((size_t)((b * NHEAD + h) * HEAD_DIM + d)) * SEQ + s;
                        g_v[vb]       = __float2half_rn(v0);
                        g_v[vb + SEQ] = __float2half_rn(v1);
                    } else {
                        size_t idx = ((size_t)((b * NHEAD + h) * SEQ + s)) * HEAD_DIM + d;
                        __half* dst = (c == 0) ? g_q : g_k;
                        __half2 hv = __floats2half2_rn(v0, v1);
                        *reinterpret_cast<__half2*>(dst + idx) = hv;
                    }
                } else {
                    *reinterpret_cast<float2*>(C + (size_t)row * N + col) =
                        make_float2(v0, v1);
                }
            }
        }
    }
}

// ---------------- flash attention (fp16 MMA, pipelined frags) ---------------
// grid: (S/128, H, B); block 256 (8 warps, 16 query rows each).
#define QTB (128 * GPB)             // 18432 B
#define KTB (64 * GPB)              // 9216 B
#define SK_OFF(s) (QTB + (s) * KTB)
#define SV_OFF(s) (QTB + 3 * KTB + (s) * KTB)
static const int ATTN_SMEM = QTB + 6 * KTB;   // 73728 B

#define A_LOADB(BF, BASE, KC) do {                                             \
    ldsm4(BF[0], (BASE) + ( 0) * GPB + boff + (KC) * 32);                      \
    ldsm4(BF[1], (BASE) + (16) * GPB + boff + (KC) * 32);                      \
    ldsm4(BF[2], (BASE) + (32) * GPB + boff + (KC) * 32);                      \
    ldsm4(BF[3], (BASE) + (48) * GPB + boff + (KC) * 32);                      \
} while (0)

#define A_MMA_S(QF, KF) do {                                                   \
    _Pragma("unroll")                                                          \
    for (int p = 0; p < 4; p++) {                                              \
        mma16(sacc[2 * p    ], QF, &KF[p][0]);                                 \
        mma16(sacc[2 * p + 1], QF, &KF[p][2]);                                 \
    }                                                                          \
} while (0)

__global__ void __launch_bounds__(256, 2)
attn_h()
{
    extern __shared__ __align__(256) char smem[];
    const uint32_t sb = sa(smem);

    const int tid = threadIdx.x, warp = tid >> 5, lane = tid & 31;

    const int qt = blockIdx.x, h = blockIdx.y, b = blockIdx.z;
    const size_t head_off = ((size_t)(b * NHEAD + h)) * SEQ * HEAD_DIM;
    const __half* Qg = g_q + head_off;
    const __half* Kg = g_k + head_off;
    const __half* Vg = g_v + head_off;   // [Dh][S]

    // K/V loaders: 64 rows x 128B, 4 threads/row
    const int kvrow = tid >> 2;
    const int kvq = (tid & 3) * 16;      // halves offset
    auto load_kv = [&](int kt, int s) {
        const __half* Ks = Kg + (size_t)(kt * 64 + kvrow) * HEAD_DIM + kvq;
        const __half* Vs = Vg + (size_t)kvrow * SEQ + kt * 64 + kvq;
        uint32_t kb = sb + SK_OFF(s) + kvrow * GPB + kvq * 2;
        uint32_t vb = sb + SV_OFF(s) + kvrow * GPB + kvq * 2;
#pragma unroll
        for (int j = 0; j < 2; j++) {
            cpa16(kb + j * 16, Ks + j * 8);
            cpa16(vb + j * 16, Vs + j * 8);
        }
        CP_COMMIT;
    };

    // Q: 128 rows x 128B, 2 threads/row (committed with kv tile 0)
    {
        const int qrow = tid >> 1;
        const int qh = (tid & 1) * 32;
        const __half* Qs = Qg + (size_t)(qt * 128 + qrow) * HEAD_DIM + qh;
        uint32_t qb = sb + qrow * GPB + qh * 2;
#pragma unroll
        for (int j = 0; j < 4; j++)
            cpa16(qb + j * 16, Qs + j * 8);
    }
    load_kv(0, 0);
    load_kv(1, 1);

    // ldmatrix per-lane offsets
    const uint32_t aoff = (uint32_t)((lane & 15) * GPB + (lane >> 4) * 16);
    const uint32_t boff = (uint32_t)(((lane & 7) + ((lane >> 4) << 3)) * GPB
                                     + ((lane >> 3) & 1) * 16);

    float oacc[8][4];
#pragma unroll
    for (int i = 0; i < 8; i++)
#pragma unroll
        for (int r = 0; r < 4; r++) oacc[i][r] = 0.f;
    float mrow[2] = {-1e30f, -1e30f};
    float lrow[2] = {0.f, 0.f};

    const float SCALE = 0.125f * 1.4426950408889634f;   // 1/sqrt(Dh) * log2(e)

    uint32_t qf[4][4];   // hoisted Q fragments (k-tile invariant)
    uint32_t kf0[4][4], kf1[4][4];

    const int NT = SEQ / 64;
    for (int kt = 0; kt < NT; kt++) {
        CP_WAIT1;
        __syncthreads();

        if (kt == 0) {
#pragma unroll
            for (int kc = 0; kc < 4; kc++)
                ldsm4(qf[kc], sb + (warp * 16) * GPB + aoff + kc * 32);
        }

        const int s = kt % 3;
        const uint32_t kb = sb + SK_OFF(s);
        const uint32_t vb = sb + SV_OFF(s);

        // S = Q K^T (16 x 64 per warp), K fragments double-buffered
        float sacc[8][4];
#pragma unroll
        for (int i = 0; i < 8; i++)
#pragma unroll
            for (int r = 0; r < 4; r++) sacc[i][r] = 0.f;

        A_LOADB(kf0, kb, 0);
        A_LOADB(kf1, kb, 1);
        A_MMA_S(qf[0], kf0);
        A_LOADB(kf0, kb, 2);
        A_MMA_S(qf[1], kf1);
        A_LOADB(kf1, kb, 3);
        A_MMA_S(qf[2], kf0);
        A_MMA_S(qf[3], kf1);

        // gmem prefetch moved off the post-barrier burst
        if (kt + 2 < NT) load_kv(kt + 2, (kt + 2) % 3);

#pragma unroll
        for (int nt = 0; nt < 8; nt++)
#pragma unroll
            for (int r = 0; r < 4; r++) sacc[nt][r] *= SCALE;

        // online softmax in log2 domain (two rows per thread: g and g+8)
#pragma unroll
        for (int rr = 0; rr < 2; rr++) {
            float mloc = -1e30f;
#pragma unroll
            for (int nt = 0; nt < 8; nt++)
                mloc = fmaxf(mloc, fmaxf(sacc[nt][rr * 2], sacc[nt][rr * 2 + 1]));
            mloc = fmaxf(mloc, __shfl_xor_sync(0xffffffffu, mloc, 1));
            mloc = fmaxf(mloc, __shfl_xor_sync(0xffffffffu, mloc, 2));
            float mnew  = fmaxf(mrow[rr], mloc);
            float alpha = ex2(mrow[rr] - mnew);
            mrow[rr] = mnew;
            float lsum = 0.f;
#pragma unroll
            for (int nt = 0; nt < 8; nt++) {
                float p0 = ex2(sacc[nt][rr * 2]     - mnew);
                float p1 = ex2(sacc[nt][rr * 2 + 1] - mnew);
                sacc[nt][rr * 2] = p0; sacc[nt][rr * 2 + 1] = p1;
                lsum += p0 + p1;
            }
            lsum += __shfl_xor_sync(0xffffffffu, lsum, 1);
            lsum += __shfl_xor_sync(0xffffffffu, lsum, 2);
            lrow[rr] = lrow[rr] * alpha + lsum;
#pragma unroll
            for (int dt = 0; dt < 8; dt++) {
                oacc[dt][rr * 2]     *= alpha;
                oacc[dt][rr * 2 + 1] *= alpha;
            }
        }

        // O += P @ V — ldsm first (latency covered by the cvt pack), then MMA
#pragma unroll
        for (int jc = 0; jc < 4; jc++) {
            uint32_t vf[4][4];
            A_LOADB(vf, vb, jc);
            uint32_t af[4];
            af[0] = h2u(sacc[2 * jc    ][0], sacc[2 * jc    ][1]);
            af[1] = h2u(sacc[2 * jc    ][2], sacc[2 * jc    ][3]);
            af[2] = h2u(sacc[2 * jc + 1][0], sacc[2 * jc + 1][1]);
            af[3] = h2u(sacc[2 * jc + 1][2], sacc[2 * jc + 1][3]);
#pragma unroll
            for (int p = 0; p < 4; p++) {
                mma16(oacc[2 * p    ], af, &vf[p][0]);
                mma16(oacc[2 * p + 1], af, &vf[p][2]);
            }
        }
    }

    // normalize; write ctx fp16 in [B,S,D] layout
    const int g = lane >> 2, qq = lane & 3;
#pragma unroll
    for (int rr = 0; rr < 2; rr++) {
        float inv = 1.f / lrow[rr];
        int s = qt * 128 + warp * 16 + g + rr * 8;
        size_t base = ((size_t)(b * SEQ + s)) * D_MODEL;
#pragma unroll
        for (int dt = 0; dt < 8; dt++) {
            int d0 = h * HEAD_DIM + dt * 8 + 2 * qq;
            __half2 hv = __floats2half2_rn(oacc[dt][rr * 2] * inv,
                                           oacc[dt][rr * 2 + 1] * inv);
            *reinterpret_cast<__half2*>(g_ctx + base + d0) = hv;
        }
    }
}

// ---------------- launch -----------------------------------------------------
extern "C" void kernel_launch(void* const* d_in, const int* in_sizes, int n_in,
                              void* d_out, int out_size)
{
    const float* x     = (const float*)d_in[0];
    const float* W_qkv = (const float*)d_in[1];
    const float* b_qkv = (const float*)d_in[2];
    const float* W_out = (const float*)d_in[3];
    const float* b_out = (const float*)d_in[4];
    float* out = (float*)d_out;

    cudaFuncSetAttribute(gemm_h<0>, cudaFuncAttributeMaxDynamicSharedMemorySize, GEMM_SMEM);
    cudaFuncSetAttribute(gemm_h<1>, cudaFuncAttributeMaxDynamicSharedMemorySize, GEMM_SMEM);
    cudaFuncSetAttribute(attn_h,    cudaFuncAttributeMaxDynamicSharedMemorySize, ATTN_SMEM);

    __half* gx; __half* gwq; __half* gwo;
    cudaGetSymbolAddress((void**)&gx,  g_x);
    cudaGetSymbolAddress((void**)&gwq, g_wqkv);
    cudaGetSymbolAddress((void**)&gwo, g_wout);

    // 0) prep: round x to fp16; transpose+round weights to [N][K] fp16
    round_h<<<2048, 256>>>(x, gx, MTOK * D_MODEL / 4);
    transpose_h<<<dim3(3 * D_MODEL / 32, D_MODEL / 32), dim3(32, 8)>>>(
        W_qkv, gwq, D_MODEL, 3 * D_MODEL);
    transpose_h<<<dim3(D_MODEL / 32, D_MODEL / 32), dim3(32, 8)>>>(
        W_out, gwo, D_MODEL, D_MODEL);

    // 1) QKV projection -> g_q/g_k ([B,H,S,Dh]), g_v ([B,H,Dh,S])
    gemm_h<0><<<dim3(3 * D_MODEL / 128, MTOK / 128), 256, GEMM_SMEM>>>(
        b_qkv, nullptr, 3 * D_MODEL, D_MODEL);

    // 2) flash attention -> ctx [B,S,D] fp16
    attn_h<<<dim3(SEQ / 128, NHEAD, BATCH), 256, ATTN_SMEM>>>();

    // 3) output projection (final fp32)
    gemm_h<1><<<dim3(D_MODEL / 128, MTOK / 128), 256, GEMM_SMEM>>>(
        b_out, out, D_MODEL, D_MODEL);
}